// round 6
// baseline (speedup 1.0000x reference)
#include <cuda_runtime.h>
#include <cuda_bf16.h>
#include <cstdint>

#define E_DIM 2048
#define T_DIM 2048
#define B_DIM 4
#define D_DIM 1024
#define BT_DIM 8192
#define N_ST 64

typedef __nv_bfloat16 bf16;
typedef unsigned long long u64;

// ---------------- scratch (device globals; no allocation allowed) ----------
static __device__ __align__(1024) float g_xz [(size_t)BT_DIM * E_DIM];
static __device__ __align__(1024) float g_sz [(size_t)BT_DIM * E_DIM];
static __device__ __align__(1024) float g_xc [(size_t)BT_DIM * E_DIM];
static __device__ __align__(1024) float g_dt [(size_t)BT_DIM * E_DIM];
static __device__ __align__(1024) float g_Bp [(size_t)BT_DIM * N_ST];
static __device__ __align__(1024) float g_Cp [(size_t)BT_DIM * N_ST];
// bf16 hi/lo splits (activations)
static __device__ __align__(1024) bf16 g_xh  [(size_t)BT_DIM * D_DIM];
static __device__ __align__(1024) bf16 g_xl  [(size_t)BT_DIM * D_DIM];
static __device__ __align__(1024) bf16 g_xch [(size_t)BT_DIM * E_DIM];
static __device__ __align__(1024) bf16 g_xcl [(size_t)BT_DIM * E_DIM];
static __device__ __align__(1024) bf16 g_ywh [(size_t)BT_DIM * E_DIM];
static __device__ __align__(1024) bf16 g_ywl [(size_t)BT_DIM * E_DIM];
// bf16 hi/lo transposed weights [N,K]
static __device__ __align__(1024) bf16 g_WinTh [(size_t)4096 * 1024];
static __device__ __align__(1024) bf16 g_WinTl [(size_t)4096 * 1024];
static __device__ __align__(1024) bf16 g_WdtTh [(size_t)2048 * 2048];
static __device__ __align__(1024) bf16 g_WdtTl [(size_t)2048 * 2048];
static __device__ __align__(1024) bf16 g_WoutTh[(size_t)1024 * 2048];
static __device__ __align__(1024) bf16 g_WoutTl[(size_t)1024 * 2048];
static __device__ __align__(1024) bf16 g_WbcH  [(size_t)128 * 2048];
static __device__ __align__(1024) bf16 g_WbcL  [(size_t)128 * 2048];

__device__ __forceinline__ float silu_f(float v) { return v / (1.f + __expf(-v)); }

// ---------------- PTX helpers ----------------------------------------------
__device__ __forceinline__ uint32_t s2u(const void* p) {
    uint32_t a;
    asm("{ .reg .u64 t; cvta.to.shared.u64 t, %1; cvt.u32.u64 %0, t; }" : "=r"(a) : "l"(p));
    return a;
}
__device__ __forceinline__ uint32_t sw128(uint32_t off) { return off ^ ((off >> 3) & 0x70); }

#define CPA16(dst, src) asm volatile("cp.async.cg.shared.global [%0], [%1], 16;" :: "r"(dst), "l"(src))
#define CPA_COMMIT()    asm volatile("cp.async.commit_group;" ::: "memory")
#define CPA_WAIT1()     asm volatile("cp.async.wait_group 1;" ::: "memory")
#define CPA_WAIT0()     asm volatile("cp.async.wait_group 0;" ::: "memory")

__device__ __forceinline__ void ldsm4(uint32_t r[4], uint32_t a) {
    asm volatile("ldmatrix.sync.aligned.m8n8.x4.shared.b16 {%0,%1,%2,%3}, [%4];"
        : "=r"(r[0]), "=r"(r[1]), "=r"(r[2]), "=r"(r[3]) : "r"(a));
}
__device__ __forceinline__ void mma_bf16(float c[4], const uint32_t a[4],
                                         uint32_t b0, uint32_t b1) {
    asm volatile(
        "mma.sync.aligned.m16n8k16.row.col.f32.bf16.bf16.f32 "
        "{%0,%1,%2,%3}, {%4,%5,%6,%7}, {%8,%9}, {%0,%1,%2,%3};"
        : "+f"(c[0]), "+f"(c[1]), "+f"(c[2]), "+f"(c[3])
        : "r"(a[0]), "r"(a[1]), "r"(a[2]), "r"(a[3]), "r"(b0), "r"(b1));
}

// packed f32x2
__device__ __forceinline__ u64 pk2(float x, float y) {
    u64 r; asm("mov.b64 %0,{%1,%2};" : "=l"(r) : "f"(x), "f"(y)); return r;
}
__device__ __forceinline__ void unpk2(float& x, float& y, u64 v) {
    asm("mov.b64 {%0,%1}, %2;" : "=f"(x), "=f"(y) : "l"(v));
}
__device__ __forceinline__ u64 f2fma(u64 a, u64 b, u64 c) {
    u64 d; asm("fma.rn.f32x2 %0,%1,%2,%3;" : "=l"(d) : "l"(a), "l"(b), "l"(c)); return d;
}
__device__ __forceinline__ u64 f2mul(u64 a, u64 b) {
    u64 d; asm("mul.rn.f32x2 %0,%1,%2;" : "=l"(d) : "l"(a), "l"(b)); return d;
}

// ============ big-tile HMMA bf16x3 GEMM: CTA 256x128, 16 warps =============
// warp tile 64x32 (wm: 4 strips of 64 rows, wn: 4 strips of 32 cols).
// A hi/lo [M,K] row-major; W hi/lo [N,K]. Double-buffered cp.async, BK=64.
// smem per stage: Ah 32K | Al 32K | Bh 16K | Bl 16K = 96KB; 2 stages = 192KB.
// MODE 0: plain fp32, stride N
// MODE 1: cols<2048 -> C0 raw; cols>=2048 -> C1 silu; stride 2048
// MODE 2: softplus(v+bias) clipped [1e-3,1e-1], stride N
#define G256_STAGE  98304
#define G256_SMEM  (2 * G256_STAGE)

template <int MODE>
__global__ __launch_bounds__(512, 1)
void gemm_mma256(const bf16* __restrict__ Ah, const bf16* __restrict__ Al,
                 const bf16* __restrict__ Bh, const bf16* __restrict__ Bl,
                 float* __restrict__ C0, float* __restrict__ C1,
                 const float* __restrict__ bias, int M, int N, int K)
{
    extern __shared__ __align__(1024) char smem[];
    const uint32_t su = s2u(smem);
    const int tid = threadIdx.x;
    const int wid = tid >> 5, lane = tid & 31;
    const int wm = wid & 3, wn = wid >> 2;     // 4 x 4 warp grid
    const int n0 = blockIdx.x * 128;
    const int m0 = blockIdx.y * 256;
    const int NT = K >> 6;

    const bf16* srcA[2] = { Ah + (size_t)m0 * K, Al + (size_t)m0 * K };
    const bf16* srcB[2] = { Bh + (size_t)n0 * K, Bl + (size_t)n0 * K };

    auto load_stage = [&](int st, int kc) {
        const uint32_t sbase = su + st * G256_STAGE;
#pragma unroll
        for (int w = 0; w < 2; w++) {           // A hi/lo: 256 rows
            const bf16* g0 = srcA[w] + kc * 64;
#pragma unroll
            for (int i = 0; i < 4; i++) {
                int c = tid + i * 512;
                int row = c >> 3, ch = c & 7;
                CPA16(sbase + w * 32768 + sw128(row * 128 + ch * 16),
                      g0 + (size_t)row * K + ch * 8);
            }
        }
#pragma unroll
        for (int w = 0; w < 2; w++) {           // B hi/lo: 128 rows
            const bf16* g0 = srcB[w] + kc * 64;
#pragma unroll
            for (int i = 0; i < 2; i++) {
                int c = tid + i * 512;
                int row = c >> 3, ch = c & 7;
                CPA16(sbase + 65536 + w * 16384 + sw128(row * 128 + ch * 16),
                      g0 + (size_t)row * K + ch * 8);
            }
        }
        CPA_COMMIT();
    };

    float acc[4][4][4];
#pragma unroll
    for (int a = 0; a < 4; a++)
#pragma unroll
        for (int b = 0; b < 4; b++)
#pragma unroll
            for (int c = 0; c < 4; c++) acc[a][b][c] = 0.f;

    load_stage(0, 0);

    const int arow = lane & 15;
    const int khalf = lane >> 4;

    for (int t = 0; t < NT; ++t) {
        if (t + 1 < NT) { load_stage((t + 1) & 1, t + 1); CPA_WAIT1(); }
        else             CPA_WAIT0();
        __syncthreads();

        const uint32_t sb = su + (t & 1) * G256_STAGE;
#pragma unroll
        for (int kk = 0; kk < 4; kk++) {
            const int kb = kk * 32 + khalf * 16;
            uint32_t bHf[2][4], bLf[2][4];
#pragma unroll
            for (int bt = 0; bt < 2; bt++) {
                int r = wn * 32 + bt * 16 + arow;
                ldsm4(bHf[bt], sb + 65536 + sw128(r * 128 + kb));
                ldsm4(bLf[bt], sb + 81920 + sw128(r * 128 + kb));
            }
#pragma unroll
            for (int mt = 0; mt < 4; mt++) {
                uint32_t aH[4], aL[4];
                int r = wm * 64 + mt * 16 + arow;
                ldsm4(aH, sb +         sw128(r * 128 + kb));
                ldsm4(aL, sb + 32768 + sw128(r * 128 + kb));
#pragma unroll
                for (int bt = 0; bt < 2; bt++)
#pragma unroll
                    for (int o = 0; o < 2; o++) {
                        const int j = bt * 2 + o;
                        mma_bf16(acc[mt][j], aH, bHf[bt][o], bHf[bt][o + 2]);
                        mma_bf16(acc[mt][j], aH, bLf[bt][o], bLf[bt][o + 2]);
                        mma_bf16(acc[mt][j], aL, bHf[bt][o], bHf[bt][o + 2]);
                    }
            }
        }
        __syncthreads();
    }

    // ---------------- epilogue from registers -------------------------------
    const int rbase = m0 + wm * 64 + (lane >> 2);
    const int cbase = n0 + wn * 32 + (lane & 3) * 2;
#pragma unroll
    for (int mt = 0; mt < 4; mt++) {
#pragma unroll
        for (int j = 0; j < 4; j++) {
            const int col = cbase + j * 8;
#pragma unroll
            for (int half = 0; half < 2; half++) {
                const int m = rbase + mt * 16 + half * 8;
                float v0 = acc[mt][j][half * 2];
                float v1 = acc[mt][j][half * 2 + 1];
                if (MODE == 0) {
                    *(float2*)(C0 + (size_t)m * N + col) = make_float2(v0, v1);
                } else if (MODE == 1) {
                    if (n0 < 2048)
                        *(float2*)(C0 + (size_t)m * 2048 + col) = make_float2(v0, v1);
                    else
                        *(float2*)(C1 + (size_t)m * 2048 + (col - 2048)) =
                            make_float2(silu_f(v0), silu_f(v1));
                } else {
                    float u0 = v0 + bias[col], u1 = v1 + bias[col + 1];
                    float s0 = (u0 > 15.f) ? u0 : log1pf(__expf(u0));
                    float s1 = (u1 > 15.f) ? u1 : log1pf(__expf(u1));
                    s0 = fminf(fmaxf(s0, 0.001f), 0.1f);
                    s1 = fminf(fmaxf(s1, 0.001f), 0.1f);
                    *(float2*)(C0 + (size_t)m * N + col) = make_float2(s0, s1);
                }
            }
        }
    }
}

// ============ small GEMM for B/C projections (CTA 128x128, 16 warps) =======
// MODE 3 semantics: N=128; cols<64 -> C0, else C1, both stride 64.
#define GEMM_SMEM (2 * 4 * 16384)

__global__ __launch_bounds__(512)
void gemm_mma_bc(const bf16* __restrict__ Ah, const bf16* __restrict__ Al,
                 const bf16* __restrict__ Bh, const bf16* __restrict__ Bl,
                 float* __restrict__ C0, float* __restrict__ C1, int K)
{
    extern __shared__ __align__(1024) char smem[];
    const uint32_t su = s2u(smem);
    const int tid = threadIdx.x;
    const int wid = tid >> 5, lane = tid & 31;
    const int wm = wid & 3, wn = wid >> 2;
    const int m0 = blockIdx.y * 128;
    const int NT = K >> 6;

    const bf16* srcs[4] = { Ah + (size_t)m0 * K, Al + (size_t)m0 * K, Bh, Bl };

    auto load_stage = [&](int st, int kc) {
        const uint32_t sbase = su + st * 65536;
#pragma unroll
        for (int w = 0; w < 4; w++) {
            const bf16* g0 = srcs[w] + kc * 64;
#pragma unroll
            for (int i = 0; i < 2; i++) {
                int c = tid + i * 512;
                int row = c >> 3, ch = c & 7;
                CPA16(sbase + w * 16384 + sw128(row * 128 + ch * 16),
                      g0 + (size_t)row * K + ch * 8);
            }
        }
        CPA_COMMIT();
    };

    float acc[2][4][4];
#pragma unroll
    for (int a = 0; a < 2; a++)
#pragma unroll
        for (int b = 0; b < 4; b++)
#pragma unroll
            for (int c = 0; c < 4; c++) acc[a][b][c] = 0.f;

    load_stage(0, 0);
    const int arow = lane & 15;
    const int khalf = lane >> 4;

    for (int t = 0; t < NT; ++t) {
        if (t + 1 < NT) { load_stage((t + 1) & 1, t + 1); CPA_WAIT1(); }
        else             CPA_WAIT0();
        __syncthreads();
        const uint32_t sb = su + (t & 1) * 65536;
#pragma unroll
        for (int kk = 0; kk < 4; kk++) {
            const int kb = kk * 32 + khalf * 16;
            uint32_t aH[2][4], aL[2][4], bHf[2][4], bLf[2][4];
#pragma unroll
            for (int mt = 0; mt < 2; mt++) {
                int r = wm * 32 + mt * 16 + arow;
                ldsm4(aH[mt], sb +         sw128(r * 128 + kb));
                ldsm4(aL[mt], sb + 16384 + sw128(r * 128 + kb));
            }
#pragma unroll
            for (int bt = 0; bt < 2; bt++) {
                int r = wn * 32 + bt * 16 + arow;
                ldsm4(bHf[bt], sb + 32768 + sw128(r * 128 + kb));
                ldsm4(bLf[bt], sb + 49152 + sw128(r * 128 + kb));
            }
#pragma unroll
            for (int mt = 0; mt < 2; mt++)
#pragma unroll
                for (int bt = 0; bt < 2; bt++)
#pragma unroll
                    for (int o = 0; o < 2; o++) {
                        const int j = bt * 2 + o;
                        mma_bf16(acc[mt][j], aH[mt], bHf[bt][o], bHf[bt][o + 2]);
                        mma_bf16(acc[mt][j], aH[mt], bLf[bt][o], bLf[bt][o + 2]);
                        mma_bf16(acc[mt][j], aL[mt], bHf[bt][o], bHf[bt][o + 2]);
                    }
        }
        __syncthreads();
    }

    const int rbase = m0 + wm * 32 + (lane >> 2);
    const int cbase = wn * 32 + (lane & 3) * 2;
#pragma unroll
    for (int mt = 0; mt < 2; mt++)
#pragma unroll
        for (int j = 0; j < 4; j++) {
            const int col = cbase + j * 8;
#pragma unroll
            for (int half = 0; half < 2; half++) {
                const int m = rbase + mt * 16 + half * 8;
                float v0 = acc[mt][j][half * 2];
                float v1 = acc[mt][j][half * 2 + 1];
                if (col < 64)
                    *(float2*)(C0 + (size_t)m * 64 + col) = make_float2(v0, v1);
                else
                    *(float2*)(C1 + (size_t)m * 64 + (col - 64)) = make_float2(v0, v1);
            }
        }
}

// ---------------- weight transpose + bf16 hi/lo split -----------------------
__global__ __launch_bounds__(256)
void tsplit_kernel(const float* __restrict__ in, bf16* __restrict__ oh,
                   bf16* __restrict__ ol, int K, int N)
{
    __shared__ float tile[32][33];
    const int n0 = blockIdx.x * 32, k0 = blockIdx.y * 32;
    const int tx = threadIdx.x & 31, ty = threadIdx.x >> 5;
#pragma unroll
    for (int i = 0; i < 4; i++)
        tile[ty + i * 8][tx] = in[(size_t)(k0 + ty + i * 8) * N + n0 + tx];
    __syncthreads();
#pragma unroll
    for (int i = 0; i < 4; i++) {
        float v = tile[tx][ty + i * 8];
        bf16 h = __float2bfloat16(v);
        float lo = v - __bfloat162float(h);
        size_t o = (size_t)(n0 + ty + i * 8) * K + k0 + tx;
        oh[o] = h;
        ol[o] = __float2bfloat16(lo);
    }
}

// ---------------- x split ----------------------------------------------------
__global__ __launch_bounds__(512)
void xsplit_kernel(const float* __restrict__ x, bf16* __restrict__ oh, bf16* __restrict__ ol)
{
    size_t i = (size_t)blockIdx.x * 512 + threadIdx.x;
    float v = x[i];
    bf16 h = __float2bfloat16(v);
    oh[i] = h;
    ol[i] = __float2bfloat16(v - __bfloat162float(h));
}

// ---------------- conv along e, weights indexed by t, + silu + split --------
__global__ __launch_bounds__(256)
void conv_silu_kernel(const float* __restrict__ xz, const float* __restrict__ Wc,
                      float* __restrict__ xc, bf16* __restrict__ xch, bf16* __restrict__ xcl)
{
    __shared__ float s[E_DIM + 4];
    const int row = blockIdx.x;           // b*T + t
    const int t = row & (T_DIM - 1);
    const int tid = threadIdx.x;
    const float* src = xz + (size_t)row * E_DIM;
#pragma unroll
    for (int j = 0; j < E_DIM / 256; ++j)
        s[tid + j * 256 + 1] = src[tid + j * 256];
    if (tid == 0) s[0] = 0.f;
    if (tid < 3) s[E_DIM + 1 + tid] = 0.f;
    __syncthreads();
    const float w0 = Wc[t], w1 = Wc[E_DIM + t], w2 = Wc[2 * E_DIM + t], w3 = Wc[3 * E_DIM + t];
    const size_t base = (size_t)row * E_DIM;
#pragma unroll
    for (int j = 0; j < E_DIM / 256; ++j) {
        int e = tid + j * 256;
        float v = w0 * s[e] + w1 * s[e + 1] + w2 * s[e + 2] + w3 * s[e + 3];
        float sv = silu_f(v);
        xc[base + e] = sv;
        bf16 h = __float2bfloat16(sv);
        xch[base + e] = h;
        xcl[base + e] = __float2bfloat16(sv - __bfloat162float(h));
    }
}

// ---------------- selective scan: warp per (b,e), f32x2 packed, decoupled ---
__global__ __launch_bounds__(512)
void scan_kernel(const float* __restrict__ xc, const float* __restrict__ dt,
                 const float* __restrict__ Bp, const float* __restrict__ Cp,
                 const float* __restrict__ sz, const float* __restrict__ A_log,
                 bf16* __restrict__ ywh, bf16* __restrict__ ywl)
{
    __shared__ float sty[32][17];       // [t mod 32][warp]
    const int tid  = threadIdx.x;
    const int warp = tid >> 5, lane = tid & 31;
    const int e0 = (blockIdx.x & 127) * 16;
    const int b  = blockIdx.x >> 7;
    const int e  = e0 + warp;
    const size_t base   = ((size_t)b * T_DIM) * E_DIM + e;
    const size_t bcbase = ((size_t)b * T_DIM) * N_ST + 2 * lane;

    const float A0 = -__expf(A_log[2 * lane]);
    const float A1 = -__expf(A_log[2 * lane + 1]);
    const u64 A2 = pk2(A0, A1);
    const u64 C24 = pk2(1.f / 24.f, 1.f / 24.f);
    const u64 C6  = pk2(1.f / 6.f, 1.f / 6.f);
    const u64 C05 = pk2(0.5f, 0.5f);
    const u64 C1  = pk2(1.f, 1.f);

    float xv  = xc[base];
    float dtv = dt[base];
    float szv = sz[base];
    float2 Bv = *(const float2*)(Bp + bcbase);
    float2 Cv = *(const float2*)(Cp + bcbase);

    u64 h = 0;
    for (int t = 0; t < T_DIM; ++t) {
        const int tn = (t + 1 < T_DIM) ? (t + 1) : t;
        const float xn  = xc[base + (size_t)tn * E_DIM];
        const float dtn = dt[base + (size_t)tn * E_DIM];
        const float szn = sz[base + (size_t)tn * E_DIM];
        const float2 Bn = *(const float2*)(Bp + bcbase + (size_t)tn * N_ST);
        const float2 Cn = *(const float2*)(Cp + bcbase + (size_t)tn * N_ST);

        const u64 dt2 = pk2(dtv, dtv);
        u64 u = f2mul(dt2, A2);
        u64 r = f2fma(u, C24, C6);
        r = f2fma(u, r, C05);
        r = f2fma(u, r, C1);
        r = f2fma(u, r, C1);
        const float dtx = dtv * xv;
        const u64 dtx2 = pk2(dtx, dtx);
        const u64 Bv2 = pk2(Bv.x, Bv.y);
        const u64 Cv2 = pk2(Cv.x, Cv.y);
        h = f2fma(r, h, f2mul(dtx2, Bv2));
        const u64 yp = f2mul(h, Cv2);
        float y0, y1;
        unpk2(y0, y1, yp);
        float y = y0 + y1;
        y += __shfl_xor_sync(0xFFFFFFFFu, y, 16);
        y += __shfl_xor_sync(0xFFFFFFFFu, y, 8);
        y += __shfl_xor_sync(0xFFFFFFFFu, y, 4);
        y += __shfl_xor_sync(0xFFFFFFFFu, y, 2);
        y += __shfl_xor_sync(0xFFFFFFFFu, y, 1);
        if (lane == 0) sty[t & 31][warp] = y * szv;

        xv = xn; dtv = dtn; szv = szn; Bv = Bn; Cv = Cn;

        if ((t & 31) == 31) {
            __syncthreads();
            const int row = tid >> 4, col = tid & 15;
            const float yv = sty[row][col];
            const bf16 hh = __float2bfloat16(yv);
            const bf16 ll = __float2bfloat16(yv - __bfloat162float(hh));
            const size_t o = ((size_t)b * T_DIM + (t - 31 + row)) * E_DIM + e0 + col;
            ywh[o] = hh;
            ywl[o] = ll;
            __syncthreads();
        }
    }
}

// ---------------------------------------------------------------------------
extern "C" void kernel_launch(void* const* d_in, const int* in_sizes, int n_in,
                              void* d_out, int out_size)
{
    (void)in_sizes; (void)n_in; (void)out_size;
    const float* x      = (const float*)d_in[0];
    const float* W_in   = (const float*)d_in[1];
    const float* W_conv = (const float*)d_in[2];
    const float* W_dt   = (const float*)d_in[3];
    const float* b_dt   = (const float*)d_in[4];
    const float* W_B    = (const float*)d_in[5];
    const float* W_C    = (const float*)d_in[6];
    const float* A_log  = (const float*)d_in[7];
    const float* W_out  = (const float*)d_in[8];
    float* out = (float*)d_out;

    float *xz, *sz, *xc, *dtb, *Bpp, *Cpp;
    bf16 *xh, *xl, *xch, *xcl, *ywh, *ywl;
    bf16 *WinTh, *WinTl, *WdtTh, *WdtTl, *WoutTh, *WoutTl, *WbcH, *WbcL;
    cudaGetSymbolAddress((void**)&xz,  g_xz);
    cudaGetSymbolAddress((void**)&sz,  g_sz);
    cudaGetSymbolAddress((void**)&xc,  g_xc);
    cudaGetSymbolAddress((void**)&dtb, g_dt);
    cudaGetSymbolAddress((void**)&Bpp, g_Bp);
    cudaGetSymbolAddress((void**)&Cpp, g_Cp);
    cudaGetSymbolAddress((void**)&xh,  g_xh);
    cudaGetSymbolAddress((void**)&xl,  g_xl);
    cudaGetSymbolAddress((void**)&xch, g_xch);
    cudaGetSymbolAddress((void**)&xcl, g_xcl);
    cudaGetSymbolAddress((void**)&ywh, g_ywh);
    cudaGetSymbolAddress((void**)&ywl, g_ywl);
    cudaGetSymbolAddress((void**)&WinTh,  g_WinTh);
    cudaGetSymbolAddress((void**)&WinTl,  g_WinTl);
    cudaGetSymbolAddress((void**)&WdtTh,  g_WdtTh);
    cudaGetSymbolAddress((void**)&WdtTl,  g_WdtTl);
    cudaGetSymbolAddress((void**)&WoutTh, g_WoutTh);
    cudaGetSymbolAddress((void**)&WoutTl, g_WoutTl);
    cudaGetSymbolAddress((void**)&WbcH,   g_WbcH);
    cudaGetSymbolAddress((void**)&WbcL,   g_WbcL);

    cudaFuncSetAttribute(gemm_mma256<0>, cudaFuncAttributeMaxDynamicSharedMemorySize, G256_SMEM);
    cudaFuncSetAttribute(gemm_mma256<1>, cudaFuncAttributeMaxDynamicSharedMemorySize, G256_SMEM);
    cudaFuncSetAttribute(gemm_mma256<2>, cudaFuncAttributeMaxDynamicSharedMemorySize, G256_SMEM);
    cudaFuncSetAttribute(gemm_mma_bc,    cudaFuncAttributeMaxDynamicSharedMemorySize, GEMM_SMEM);

    // 0) prep: split x, transpose+split weights
    xsplit_kernel<<<(BT_DIM * D_DIM) / 512, 512>>>(x, xh, xl);
    tsplit_kernel<<<dim3(4096 / 32, 1024 / 32), 256>>>(W_in,  WinTh,  WinTl,  1024, 4096);
    tsplit_kernel<<<dim3(2048 / 32, 2048 / 32), 256>>>(W_dt,  WdtTh,  WdtTl,  2048, 2048);
    tsplit_kernel<<<dim3(1024 / 32, 2048 / 32), 256>>>(W_out, WoutTh, WoutTl, 2048, 1024);
    tsplit_kernel<<<dim3(64 / 32, 2048 / 32), 256>>>(W_B, WbcH,             WbcL,             2048, 64);
    tsplit_kernel<<<dim3(64 / 32, 2048 / 32), 256>>>(W_C, WbcH + 64 * 2048, WbcL + 64 * 2048, 2048, 64);

    // 1) in-projection: [8192,1024] @ [1024,4096] -> xz raw / sz silu
    gemm_mma256<1><<<dim3(4096 / 128, BT_DIM / 256), 512, G256_SMEM>>>(
        xh, xl, WinTh, WinTl, xz, sz, nullptr, BT_DIM, 4096, 1024);

    // 2) conv along e + silu + bf16 split
    conv_silu_kernel<<<BT_DIM, 256>>>(xz, W_conv, xc, xch, xcl);

    // 3) dt projection + softplus + clip
    gemm_mma256<2><<<dim3(E_DIM / 128, BT_DIM / 256), 512, G256_SMEM>>>(
        xch, xcl, WdtTh, WdtTl, dtb, nullptr, b_dt, BT_DIM, E_DIM, E_DIM);

    // 4) B/C projections (fused into one N=128 GEMM)
    gemm_mma_bc<<<dim3(1, BT_DIM / 128), 512, GEMM_SMEM>>>(
        xch, xcl, WbcH, WbcL, Bpp, Cpp, 2048);

    // 5) selective scan (fuses y * silu(z), emits bf16 hi/lo)
    scan_kernel<<<B_DIM * (E_DIM / 16), 512>>>(xc, dtb, Bpp, Cpp, sz, A_log, ywh, ywl);

    // 6) out projection -> d_out
    gemm_mma256<0><<<dim3(D_DIM / 128, BT_DIM / 256), 512, G256_SMEM>>>(
        ywh, ywl, WoutTh, WoutTl, out, nullptr, nullptr, BT_DIM, D_DIM, E_DIM);
}

// round 7
// speedup vs baseline: 1.0271x; 1.0271x over previous
#include <cuda_runtime.h>
#include <cuda_bf16.h>
#include <cstdint>

#define E_DIM 2048
#define T_DIM 2048
#define B_DIM 4
#define D_DIM 1024
#define BT_DIM 8192
#define N_ST 64

typedef __nv_bfloat16 bf16;
typedef unsigned long long u64;

// ---------------- scratch (device globals; no allocation allowed) ----------
static __device__ __align__(1024) float g_xz [(size_t)BT_DIM * E_DIM];
static __device__ __align__(1024) float g_sz [(size_t)BT_DIM * E_DIM];
static __device__ __align__(1024) float g_xc [(size_t)BT_DIM * E_DIM];
static __device__ __align__(1024) float g_dt [(size_t)BT_DIM * E_DIM];
static __device__ __align__(1024) float g_Bp [(size_t)BT_DIM * N_ST];
static __device__ __align__(1024) float g_Cp [(size_t)BT_DIM * N_ST];
// bf16 hi/lo splits (activations)
static __device__ __align__(1024) bf16 g_xh  [(size_t)BT_DIM * D_DIM];
static __device__ __align__(1024) bf16 g_xl  [(size_t)BT_DIM * D_DIM];
static __device__ __align__(1024) bf16 g_xch [(size_t)BT_DIM * E_DIM];
static __device__ __align__(1024) bf16 g_xcl [(size_t)BT_DIM * E_DIM];
static __device__ __align__(1024) bf16 g_ywh [(size_t)BT_DIM * E_DIM];
static __device__ __align__(1024) bf16 g_ywl [(size_t)BT_DIM * E_DIM];
// bf16 hi/lo transposed weights [N,K]
static __device__ __align__(1024) bf16 g_WinTh [(size_t)4096 * 1024];
static __device__ __align__(1024) bf16 g_WinTl [(size_t)4096 * 1024];
static __device__ __align__(1024) bf16 g_WdtTh [(size_t)2048 * 2048];
static __device__ __align__(1024) bf16 g_WdtTl [(size_t)2048 * 2048];
static __device__ __align__(1024) bf16 g_WoutTh[(size_t)1024 * 2048];
static __device__ __align__(1024) bf16 g_WoutTl[(size_t)1024 * 2048];
static __device__ __align__(1024) bf16 g_WbcH  [(size_t)128 * 2048];
static __device__ __align__(1024) bf16 g_WbcL  [(size_t)128 * 2048];

__device__ __forceinline__ float silu_f(float v) { return v / (1.f + __expf(-v)); }

// ---------------- PTX helpers ----------------------------------------------
__device__ __forceinline__ uint32_t s2u(const void* p) {
    uint32_t a;
    asm("{ .reg .u64 t; cvta.to.shared.u64 t, %1; cvt.u32.u64 %0, t; }" : "=r"(a) : "l"(p));
    return a;
}
__device__ __forceinline__ uint32_t sw128(uint32_t off) { return off ^ ((off >> 3) & 0x70); }

#define CPA16(dst, src) asm volatile("cp.async.cg.shared.global [%0], [%1], 16;" :: "r"(dst), "l"(src))
#define CPA_COMMIT()    asm volatile("cp.async.commit_group;" ::: "memory")
#define CPA_WAIT1()     asm volatile("cp.async.wait_group 1;" ::: "memory")
#define CPA_WAIT0()     asm volatile("cp.async.wait_group 0;" ::: "memory")

__device__ __forceinline__ void ldsm4(uint32_t r[4], uint32_t a) {
    asm volatile("ldmatrix.sync.aligned.m8n8.x4.shared.b16 {%0,%1,%2,%3}, [%4];"
        : "=r"(r[0]), "=r"(r[1]), "=r"(r[2]), "=r"(r[3]) : "r"(a));
}
__device__ __forceinline__ void mma_bf16(float c[4], const uint32_t a[4],
                                         uint32_t b0, uint32_t b1) {
    asm volatile(
        "mma.sync.aligned.m16n8k16.row.col.f32.bf16.bf16.f32 "
        "{%0,%1,%2,%3}, {%4,%5,%6,%7}, {%8,%9}, {%0,%1,%2,%3};"
        : "+f"(c[0]), "+f"(c[1]), "+f"(c[2]), "+f"(c[3])
        : "r"(a[0]), "r"(a[1]), "r"(a[2]), "r"(a[3]), "r"(b0), "r"(b1));
}

// packed f32x2
__device__ __forceinline__ u64 pk2(float x, float y) {
    u64 r; asm("mov.b64 %0,{%1,%2};" : "=l"(r) : "f"(x), "f"(y)); return r;
}
__device__ __forceinline__ void unpk2(float& x, float& y, u64 v) {
    asm("mov.b64 {%0,%1}, %2;" : "=f"(x), "=f"(y) : "l"(v));
}
__device__ __forceinline__ u64 f2fma(u64 a, u64 b, u64 c) {
    u64 d; asm("fma.rn.f32x2 %0,%1,%2,%3;" : "=l"(d) : "l"(a), "l"(b), "l"(c)); return d;
}
__device__ __forceinline__ u64 f2mul(u64 a, u64 b) {
    u64 d; asm("mul.rn.f32x2 %0,%1,%2;" : "=l"(d) : "l"(a), "l"(b)); return d;
}

// ---------------- HMMA bf16x3 GEMM: C[M,N] = A[M,K] * W[K,N] ---------------
// CTA 128x128, BK=64, 16 warps (4x4), warp tile 32x32, THREE-stage cp.async.
// A hi/lo [M,K] row-major; W hi/lo [N,K] (pre-transposed).
// MODE 0: plain fp32 store, stride N
// MODE 1: cols<2048 -> C0 raw, cols>=2048 -> C1 = silu, stride 2048
// MODE 2: softplus(v + bias[col]) clipped [1e-3,1e-1], stride N
#define G_STAGE 65536
#define GEMM_SMEM (3 * G_STAGE)

template <int MODE>
__global__ __launch_bounds__(512)
void gemm_mma(const bf16* __restrict__ Ah, const bf16* __restrict__ Al,
              const bf16* __restrict__ Bh, const bf16* __restrict__ Bl,
              float* __restrict__ C0, float* __restrict__ C1,
              const float* __restrict__ bias, int M, int N, int K)
{
    extern __shared__ __align__(1024) char smem[];
    const uint32_t su = s2u(smem);
    const int tid = threadIdx.x;
    const int wid = tid >> 5, lane = tid & 31;
    const int wm = wid & 3, wn = wid >> 2;     // 4 x 4 warp grid
    const int n0 = blockIdx.x * 128;
    const int m0 = blockIdx.y * 128;
    const int NT = K >> 6;

    const bf16* srcs[4] = { Ah + (size_t)m0 * K, Al + (size_t)m0 * K,
                            Bh + (size_t)n0 * K, Bl + (size_t)n0 * K };

    auto load_stage = [&](int st, int kc) {
        const uint32_t sbase = su + st * G_STAGE;
#pragma unroll
        for (int w = 0; w < 4; w++) {
            const bf16* g0 = srcs[w] + kc * 64;
#pragma unroll
            for (int i = 0; i < 2; i++) {
                int c = tid + i * 512;
                int row = c >> 3, ch = c & 7;
                CPA16(sbase + w * 16384 + sw128(row * 128 + ch * 16),
                      g0 + (size_t)row * K + ch * 8);
            }
        }
        CPA_COMMIT();
    };

    float acc[2][4][4];
#pragma unroll
    for (int a = 0; a < 2; a++)
#pragma unroll
        for (int b = 0; b < 4; b++)
#pragma unroll
            for (int c = 0; c < 4; c++) acc[a][b][c] = 0.f;

    load_stage(0, 0);
    if (NT > 1) load_stage(1, 1);

    const int arow = lane & 15;
    const int khalf = lane >> 4;
    int sidx = 0;                 // stage buffer index of stage t

    for (int t = 0; t < NT; ++t) {
        if (t + 1 < NT) CPA_WAIT1(); else CPA_WAIT0();
        __syncthreads();

        if (t + 2 < NT) {
            int nb = sidx + 2; if (nb >= 3) nb -= 3;
            load_stage(nb, t + 2);
        }

        const uint32_t sb = su + sidx * G_STAGE;
#pragma unroll
        for (int kk = 0; kk < 4; kk++) {
            const int kb = kk * 32 + khalf * 16;
            uint32_t aH[2][4], aL[2][4], bHf[2][4], bLf[2][4];
#pragma unroll
            for (int mt = 0; mt < 2; mt++) {
                int r = wm * 32 + mt * 16 + arow;
                ldsm4(aH[mt], sb +         sw128(r * 128 + kb));
                ldsm4(aL[mt], sb + 16384 + sw128(r * 128 + kb));
            }
#pragma unroll
            for (int bt = 0; bt < 2; bt++) {
                int r = wn * 32 + bt * 16 + arow;
                ldsm4(bHf[bt], sb + 32768 + sw128(r * 128 + kb));
                ldsm4(bLf[bt], sb + 49152 + sw128(r * 128 + kb));
            }
#pragma unroll
            for (int mt = 0; mt < 2; mt++)
#pragma unroll
                for (int bt = 0; bt < 2; bt++)
#pragma unroll
                    for (int o = 0; o < 2; o++) {
                        const int j = bt * 2 + o;
                        mma_bf16(acc[mt][j], aH[mt], bHf[bt][o], bHf[bt][o + 2]);
                        mma_bf16(acc[mt][j], aH[mt], bLf[bt][o], bLf[bt][o + 2]);
                        mma_bf16(acc[mt][j], aL[mt], bHf[bt][o], bHf[bt][o + 2]);
                    }
        }
        __syncthreads();
        sidx = (sidx + 1 == 3) ? 0 : sidx + 1;
    }

    // ---------------- epilogue from registers -------------------------------
    const int rbase = m0 + wm * 32 + (lane >> 2);
    const int cbase = n0 + wn * 32 + (lane & 3) * 2;
#pragma unroll
    for (int mt = 0; mt < 2; mt++) {
#pragma unroll
        for (int j = 0; j < 4; j++) {
            const int col = cbase + j * 8;
#pragma unroll
            for (int half = 0; half < 2; half++) {
                const int m = rbase + mt * 16 + half * 8;
                float v0 = acc[mt][j][half * 2];
                float v1 = acc[mt][j][half * 2 + 1];
                if (MODE == 0) {
                    *(float2*)(C0 + (size_t)m * N + col) = make_float2(v0, v1);
                } else if (MODE == 1) {
                    if (n0 < 2048)
                        *(float2*)(C0 + (size_t)m * 2048 + col) = make_float2(v0, v1);
                    else
                        *(float2*)(C1 + (size_t)m * 2048 + (col - 2048)) =
                            make_float2(silu_f(v0), silu_f(v1));
                } else {
                    float u0 = v0 + bias[col], u1 = v1 + bias[col + 1];
                    float s0 = (u0 > 15.f) ? u0 : log1pf(__expf(u0));
                    float s1 = (u1 > 15.f) ? u1 : log1pf(__expf(u1));
                    s0 = fminf(fmaxf(s0, 0.001f), 0.1f);
                    s1 = fminf(fmaxf(s1, 0.001f), 0.1f);
                    *(float2*)(C0 + (size_t)m * N + col) = make_float2(s0, s1);
                }
            }
        }
    }
}

// ============ small GEMM for B/C projections (CTA 128x128, 16 warps) =======
__global__ __launch_bounds__(512)
void gemm_mma_bc(const bf16* __restrict__ Ah, const bf16* __restrict__ Al,
                 const bf16* __restrict__ Bh, const bf16* __restrict__ Bl,
                 float* __restrict__ C0, float* __restrict__ C1, int K)
{
    extern __shared__ __align__(1024) char smem[];
    const uint32_t su = s2u(smem);
    const int tid = threadIdx.x;
    const int wid = tid >> 5, lane = tid & 31;
    const int wm = wid & 3, wn = wid >> 2;
    const int m0 = blockIdx.y * 128;
    const int NT = K >> 6;

    const bf16* srcs[4] = { Ah + (size_t)m0 * K, Al + (size_t)m0 * K, Bh, Bl };

    auto load_stage = [&](int st, int kc) {
        const uint32_t sbase = su + st * G_STAGE;
#pragma unroll
        for (int w = 0; w < 4; w++) {
            const bf16* g0 = srcs[w] + kc * 64;
#pragma unroll
            for (int i = 0; i < 2; i++) {
                int c = tid + i * 512;
                int row = c >> 3, ch = c & 7;
                CPA16(sbase + w * 16384 + sw128(row * 128 + ch * 16),
                      g0 + (size_t)row * K + ch * 8);
            }
        }
        CPA_COMMIT();
    };

    float acc[2][4][4];
#pragma unroll
    for (int a = 0; a < 2; a++)
#pragma unroll
        for (int b = 0; b < 4; b++)
#pragma unroll
            for (int c = 0; c < 4; c++) acc[a][b][c] = 0.f;

    load_stage(0, 0);
    if (NT > 1) load_stage(1, 1);
    const int arow = lane & 15;
    const int khalf = lane >> 4;
    int sidx = 0;

    for (int t = 0; t < NT; ++t) {
        if (t + 1 < NT) CPA_WAIT1(); else CPA_WAIT0();
        __syncthreads();
        if (t + 2 < NT) {
            int nb = sidx + 2; if (nb >= 3) nb -= 3;
            load_stage(nb, t + 2);
        }
        const uint32_t sb = su + sidx * G_STAGE;
#pragma unroll
        for (int kk = 0; kk < 4; kk++) {
            const int kb = kk * 32 + khalf * 16;
            uint32_t aH[2][4], aL[2][4], bHf[2][4], bLf[2][4];
#pragma unroll
            for (int mt = 0; mt < 2; mt++) {
                int r = wm * 32 + mt * 16 + arow;
                ldsm4(aH[mt], sb +         sw128(r * 128 + kb));
                ldsm4(aL[mt], sb + 16384 + sw128(r * 128 + kb));
            }
#pragma unroll
            for (int bt = 0; bt < 2; bt++) {
                int r = wn * 32 + bt * 16 + arow;
                ldsm4(bHf[bt], sb + 32768 + sw128(r * 128 + kb));
                ldsm4(bLf[bt], sb + 49152 + sw128(r * 128 + kb));
            }
#pragma unroll
            for (int mt = 0; mt < 2; mt++)
#pragma unroll
                for (int bt = 0; bt < 2; bt++)
#pragma unroll
                    for (int o = 0; o < 2; o++) {
                        const int j = bt * 2 + o;
                        mma_bf16(acc[mt][j], aH[mt], bHf[bt][o], bHf[bt][o + 2]);
                        mma_bf16(acc[mt][j], aH[mt], bLf[bt][o], bLf[bt][o + 2]);
                        mma_bf16(acc[mt][j], aL[mt], bHf[bt][o], bHf[bt][o + 2]);
                    }
        }
        __syncthreads();
        sidx = (sidx + 1 == 3) ? 0 : sidx + 1;
    }

    const int rbase = m0 + wm * 32 + (lane >> 2);
    const int cbase = wn * 32 + (lane & 3) * 2;
#pragma unroll
    for (int mt = 0; mt < 2; mt++)
#pragma unroll
        for (int j = 0; j < 4; j++) {
            const int col = cbase + j * 8;
#pragma unroll
            for (int half = 0; half < 2; half++) {
                const int m = rbase + mt * 16 + half * 8;
                float v0 = acc[mt][j][half * 2];
                float v1 = acc[mt][j][half * 2 + 1];
                if (col < 64)
                    *(float2*)(C0 + (size_t)m * 64 + col) = make_float2(v0, v1);
                else
                    *(float2*)(C1 + (size_t)m * 64 + (col - 64)) = make_float2(v0, v1);
            }
        }
}

// ---------------- weight transpose + bf16 hi/lo split -----------------------
__global__ __launch_bounds__(256)
void tsplit_kernel(const float* __restrict__ in, bf16* __restrict__ oh,
                   bf16* __restrict__ ol, int K, int N)
{
    __shared__ float tile[32][33];
    const int n0 = blockIdx.x * 32, k0 = blockIdx.y * 32;
    const int tx = threadIdx.x & 31, ty = threadIdx.x >> 5;
#pragma unroll
    for (int i = 0; i < 4; i++)
        tile[ty + i * 8][tx] = in[(size_t)(k0 + ty + i * 8) * N + n0 + tx];
    __syncthreads();
#pragma unroll
    for (int i = 0; i < 4; i++) {
        float v = tile[tx][ty + i * 8];
        bf16 h = __float2bfloat16(v);
        float lo = v - __bfloat162float(h);
        size_t o = (size_t)(n0 + ty + i * 8) * K + k0 + tx;
        oh[o] = h;
        ol[o] = __float2bfloat16(lo);
    }
}

// ---------------- x split ----------------------------------------------------
__global__ __launch_bounds__(512)
void xsplit_kernel(const float* __restrict__ x, bf16* __restrict__ oh, bf16* __restrict__ ol)
{
    size_t i = (size_t)blockIdx.x * 512 + threadIdx.x;
    float v = x[i];
    bf16 h = __float2bfloat16(v);
    oh[i] = h;
    ol[i] = __float2bfloat16(v - __bfloat162float(h));
}

// ---------------- conv along e, weights indexed by t, + silu + split --------
__global__ __launch_bounds__(256)
void conv_silu_kernel(const float* __restrict__ xz, const float* __restrict__ Wc,
                      float* __restrict__ xc, bf16* __restrict__ xch, bf16* __restrict__ xcl)
{
    __shared__ float s[E_DIM + 4];
    const int row = blockIdx.x;           // b*T + t
    const int t = row & (T_DIM - 1);
    const int tid = threadIdx.x;
    const float* src = xz + (size_t)row * E_DIM;
#pragma unroll
    for (int j = 0; j < E_DIM / 256; ++j)
        s[tid + j * 256 + 1] = src[tid + j * 256];
    if (tid == 0) s[0] = 0.f;
    if (tid < 3) s[E_DIM + 1 + tid] = 0.f;
    __syncthreads();
    const float w0 = Wc[t], w1 = Wc[E_DIM + t], w2 = Wc[2 * E_DIM + t], w3 = Wc[3 * E_DIM + t];
    const size_t base = (size_t)row * E_DIM;
#pragma unroll
    for (int j = 0; j < E_DIM / 256; ++j) {
        int e = tid + j * 256;
        float v = w0 * s[e] + w1 * s[e + 1] + w2 * s[e + 2] + w3 * s[e + 3];
        float sv = silu_f(v);
        xc[base + e] = sv;
        bf16 h = __float2bfloat16(sv);
        xch[base + e] = h;
        xcl[base + e] = __float2bfloat16(sv - __bfloat162float(h));
    }
}

// ---------------- selective scan: warp per (b,e), f32x2 packed, decoupled ---
__global__ __launch_bounds__(512)
void scan_kernel(const float* __restrict__ xc, const float* __restrict__ dt,
                 const float* __restrict__ Bp, const float* __restrict__ Cp,
                 const float* __restrict__ sz, const float* __restrict__ A_log,
                 bf16* __restrict__ ywh, bf16* __restrict__ ywl)
{
    __shared__ float sty[32][17];       // [t mod 32][warp]
    const int tid  = threadIdx.x;
    const int warp = tid >> 5, lane = tid & 31;
    const int e0 = (blockIdx.x & 127) * 16;
    const int b  = blockIdx.x >> 7;
    const int e  = e0 + warp;
    const size_t base   = ((size_t)b * T_DIM) * E_DIM + e;
    const size_t bcbase = ((size_t)b * T_DIM) * N_ST + 2 * lane;

    const float A0 = -__expf(A_log[2 * lane]);
    const float A1 = -__expf(A_log[2 * lane + 1]);
    const u64 A2 = pk2(A0, A1);
    const u64 C24 = pk2(1.f / 24.f, 1.f / 24.f);
    const u64 C6  = pk2(1.f / 6.f, 1.f / 6.f);
    const u64 C05 = pk2(0.5f, 0.5f);
    const u64 C1  = pk2(1.f, 1.f);

    float xv  = xc[base];
    float dtv = dt[base];
    float szv = sz[base];
    float2 Bv = *(const float2*)(Bp + bcbase);
    float2 Cv = *(const float2*)(Cp + bcbase);

    u64 h = 0;
    for (int t = 0; t < T_DIM; ++t) {
        const int tn = (t + 1 < T_DIM) ? (t + 1) : t;
        const float xn  = xc[base + (size_t)tn * E_DIM];
        const float dtn = dt[base + (size_t)tn * E_DIM];
        const float szn = sz[base + (size_t)tn * E_DIM];
        const float2 Bn = *(const float2*)(Bp + bcbase + (size_t)tn * N_ST);
        const float2 Cn = *(const float2*)(Cp + bcbase + (size_t)tn * N_ST);

        const u64 dt2 = pk2(dtv, dtv);
        u64 u = f2mul(dt2, A2);
        u64 r = f2fma(u, C24, C6);
        r = f2fma(u, r, C05);
        r = f2fma(u, r, C1);
        r = f2fma(u, r, C1);
        const float dtx = dtv * xv;
        const u64 dtx2 = pk2(dtx, dtx);
        const u64 Bv2 = pk2(Bv.x, Bv.y);
        const u64 Cv2 = pk2(Cv.x, Cv.y);
        h = f2fma(r, h, f2mul(dtx2, Bv2));
        const u64 yp = f2mul(h, Cv2);
        float y0, y1;
        unpk2(y0, y1, yp);
        float y = y0 + y1;
        y += __shfl_xor_sync(0xFFFFFFFFu, y, 16);
        y += __shfl_xor_sync(0xFFFFFFFFu, y, 8);
        y += __shfl_xor_sync(0xFFFFFFFFu, y, 4);
        y += __shfl_xor_sync(0xFFFFFFFFu, y, 2);
        y += __shfl_xor_sync(0xFFFFFFFFu, y, 1);
        if (lane == 0) sty[t & 31][warp] = y * szv;

        xv = xn; dtv = dtn; szv = szn; Bv = Bn; Cv = Cn;

        if ((t & 31) == 31) {
            __syncthreads();
            const int row = tid >> 4, col = tid & 15;
            const float yv = sty[row][col];
            const bf16 hh = __float2bfloat16(yv);
            const bf16 ll = __float2bfloat16(yv - __bfloat162float(hh));
            const size_t o = ((size_t)b * T_DIM + (t - 31 + row)) * E_DIM + e0 + col;
            ywh[o] = hh;
            ywl[o] = ll;
            __syncthreads();
        }
    }
}

// ---------------------------------------------------------------------------
extern "C" void kernel_launch(void* const* d_in, const int* in_sizes, int n_in,
                              void* d_out, int out_size)
{
    (void)in_sizes; (void)n_in; (void)out_size;
    const float* x      = (const float*)d_in[0];
    const float* W_in   = (const float*)d_in[1];
    const float* W_conv = (const float*)d_in[2];
    const float* W_dt   = (const float*)d_in[3];
    const float* b_dt   = (const float*)d_in[4];
    const float* W_B    = (const float*)d_in[5];
    const float* W_C    = (const float*)d_in[6];
    const float* A_log  = (const float*)d_in[7];
    const float* W_out  = (const float*)d_in[8];
    float* out = (float*)d_out;

    float *xz, *sz, *xc, *dtb, *Bpp, *Cpp;
    bf16 *xh, *xl, *xch, *xcl, *ywh, *ywl;
    bf16 *WinTh, *WinTl, *WdtTh, *WdtTl, *WoutTh, *WoutTl, *WbcH, *WbcL;
    cudaGetSymbolAddress((void**)&xz,  g_xz);
    cudaGetSymbolAddress((void**)&sz,  g_sz);
    cudaGetSymbolAddress((void**)&xc,  g_xc);
    cudaGetSymbolAddress((void**)&dtb, g_dt);
    cudaGetSymbolAddress((void**)&Bpp, g_Bp);
    cudaGetSymbolAddress((void**)&Cpp, g_Cp);
    cudaGetSymbolAddress((void**)&xh,  g_xh);
    cudaGetSymbolAddress((void**)&xl,  g_xl);
    cudaGetSymbolAddress((void**)&xch, g_xch);
    cudaGetSymbolAddress((void**)&xcl, g_xcl);
    cudaGetSymbolAddress((void**)&ywh, g_ywh);
    cudaGetSymbolAddress((void**)&ywl, g_ywl);
    cudaGetSymbolAddress((void**)&WinTh,  g_WinTh);
    cudaGetSymbolAddress((void**)&WinTl,  g_WinTl);
    cudaGetSymbolAddress((void**)&WdtTh,  g_WdtTh);
    cudaGetSymbolAddress((void**)&WdtTl,  g_WdtTl);
    cudaGetSymbolAddress((void**)&WoutTh, g_WoutTh);
    cudaGetSymbolAddress((void**)&WoutTl, g_WoutTl);
    cudaGetSymbolAddress((void**)&WbcH,   g_WbcH);
    cudaGetSymbolAddress((void**)&WbcL,   g_WbcL);

    cudaFuncSetAttribute(gemm_mma<0>, cudaFuncAttributeMaxDynamicSharedMemorySize, GEMM_SMEM);
    cudaFuncSetAttribute(gemm_mma<1>, cudaFuncAttributeMaxDynamicSharedMemorySize, GEMM_SMEM);
    cudaFuncSetAttribute(gemm_mma<2>, cudaFuncAttributeMaxDynamicSharedMemorySize, GEMM_SMEM);
    cudaFuncSetAttribute(gemm_mma_bc, cudaFuncAttributeMaxDynamicSharedMemorySize, GEMM_SMEM);

    // launch order arranged so launch index 5 (ncu -s 5) = dt-projection GEMM
    // 0) x split
    xsplit_kernel<<<(BT_DIM * D_DIM) / 512, 512>>>(x, xh, xl);
    // 1) W_in transpose+split
    tsplit_kernel<<<dim3(4096 / 32, 1024 / 32), 256>>>(W_in, WinTh, WinTl, 1024, 4096);
    // 2) in-projection
    gemm_mma<1><<<dim3(4096 / 128, BT_DIM / 128), 512, GEMM_SMEM>>>(
        xh, xl, WinTh, WinTl, xz, sz, nullptr, BT_DIM, 4096, 1024);
    // 3) conv along e + silu + bf16 split
    conv_silu_kernel<<<BT_DIM, 256>>>(xz, W_conv, xc, xch, xcl);
    // 4) W_dt transpose+split
    tsplit_kernel<<<dim3(2048 / 32, 2048 / 32), 256>>>(W_dt, WdtTh, WdtTl, 2048, 2048);
    // 5) dt projection + softplus + clip   <-- ncu capture target
    gemm_mma<2><<<dim3(E_DIM / 128, BT_DIM / 128), 512, GEMM_SMEM>>>(
        xch, xcl, WdtTh, WdtTl, dtb, nullptr, b_dt, BT_DIM, E_DIM, E_DIM);
    // 6-7) W_B / W_C splits
    tsplit_kernel<<<dim3(64 / 32, 2048 / 32), 256>>>(W_B, WbcH,             WbcL,             2048, 64);
    tsplit_kernel<<<dim3(64 / 32, 2048 / 32), 256>>>(W_C, WbcH + 64 * 2048, WbcL + 64 * 2048, 2048, 64);
    // 8) B/C projections
    gemm_mma_bc<<<dim3(1, BT_DIM / 128), 512, GEMM_SMEM>>>(
        xch, xcl, WbcH, WbcL, Bpp, Cpp, 2048);
    // 9) W_out split
    tsplit_kernel<<<dim3(1024 / 32, 2048 / 32), 256>>>(W_out, WoutTh, WoutTl, 2048, 1024);
    // 10) selective scan
    scan_kernel<<<B_DIM * (E_DIM / 16), 512>>>(xc, dtb, Bpp, Cpp, sz, A_log, ywh, ywl);
    // 11) out projection -> d_out
    gemm_mma<0><<<dim3(D_DIM / 128, BT_DIM / 128), 512, GEMM_SMEM>>>(
        ywh, ywl, WoutTh, WoutTl, out, nullptr, nullptr, BT_DIM, D_DIM, E_DIM);
}

// round 8
// speedup vs baseline: 1.0813x; 1.0528x over previous
#include <cuda_runtime.h>
#include <cuda_bf16.h>
#include <cstdint>

#define E_DIM 2048
#define T_DIM 2048
#define B_DIM 4
#define D_DIM 1024
#define BT_DIM 8192
#define N_ST 64

typedef __nv_bfloat16 bf16;
typedef unsigned long long u64;

// ---------------- scratch (device globals; no allocation allowed) ----------
static __device__ __align__(1024) float g_xz [(size_t)BT_DIM * E_DIM];
static __device__ __align__(1024) float g_sz [(size_t)BT_DIM * E_DIM];
static __device__ __align__(1024) float g_xc [(size_t)BT_DIM * E_DIM];
static __device__ __align__(1024) float g_dt [(size_t)BT_DIM * E_DIM];
static __device__ __align__(1024) float g_Bp [(size_t)BT_DIM * N_ST];
static __device__ __align__(1024) float g_Cp [(size_t)BT_DIM * N_ST];
// bf16 hi/lo splits (activations)
static __device__ __align__(1024) bf16 g_xh  [(size_t)BT_DIM * D_DIM];
static __device__ __align__(1024) bf16 g_xl  [(size_t)BT_DIM * D_DIM];
static __device__ __align__(1024) bf16 g_xch [(size_t)BT_DIM * E_DIM];
static __device__ __align__(1024) bf16 g_xcl [(size_t)BT_DIM * E_DIM];
static __device__ __align__(1024) bf16 g_ywh [(size_t)BT_DIM * E_DIM];
static __device__ __align__(1024) bf16 g_ywl [(size_t)BT_DIM * E_DIM];
// bf16 hi/lo transposed weights [N,K]
static __device__ __align__(1024) bf16 g_WinTh [(size_t)4096 * 1024];
static __device__ __align__(1024) bf16 g_WinTl [(size_t)4096 * 1024];
static __device__ __align__(1024) bf16 g_WdtTh [(size_t)2048 * 2048];
static __device__ __align__(1024) bf16 g_WdtTl [(size_t)2048 * 2048];
static __device__ __align__(1024) bf16 g_WoutTh[(size_t)1024 * 2048];
static __device__ __align__(1024) bf16 g_WoutTl[(size_t)1024 * 2048];
static __device__ __align__(1024) bf16 g_WbcH  [(size_t)128 * 2048];
static __device__ __align__(1024) bf16 g_WbcL  [(size_t)128 * 2048];

__device__ __forceinline__ float silu_f(float v) { return v / (1.f + __expf(-v)); }

// ---------------- PTX helpers ----------------------------------------------
__device__ __forceinline__ uint32_t s2u(const void* p) {
    uint32_t a;
    asm("{ .reg .u64 t; cvta.to.shared.u64 t, %1; cvt.u32.u64 %0, t; }" : "=r"(a) : "l"(p));
    return a;
}
__device__ __forceinline__ uint32_t sw128(uint32_t off) { return off ^ ((off >> 3) & 0x70); }

#define CPA16(dst, src) asm volatile("cp.async.cg.shared.global [%0], [%1], 16;" :: "r"(dst), "l"(src))
#define CPA_COMMIT()    asm volatile("cp.async.commit_group;" ::: "memory")
#define CPA_WAIT1()     asm volatile("cp.async.wait_group 1;" ::: "memory")
#define CPA_WAIT0()     asm volatile("cp.async.wait_group 0;" ::: "memory")

__device__ __forceinline__ void ldsm4(uint32_t r[4], uint32_t a) {
    asm volatile("ldmatrix.sync.aligned.m8n8.x4.shared.b16 {%0,%1,%2,%3}, [%4];"
        : "=r"(r[0]), "=r"(r[1]), "=r"(r[2]), "=r"(r[3]) : "r"(a));
}
__device__ __forceinline__ void mma_bf16(float c[4], const uint32_t a[4],
                                         uint32_t b0, uint32_t b1) {
    asm volatile(
        "mma.sync.aligned.m16n8k16.row.col.f32.bf16.bf16.f32 "
        "{%0,%1,%2,%3}, {%4,%5,%6,%7}, {%8,%9}, {%0,%1,%2,%3};"
        : "+f"(c[0]), "+f"(c[1]), "+f"(c[2]), "+f"(c[3])
        : "r"(a[0]), "r"(a[1]), "r"(a[2]), "r"(a[3]), "r"(b0), "r"(b1));
}

// packed f32x2
__device__ __forceinline__ u64 pk2(float x, float y) {
    u64 r; asm("mov.b64 %0,{%1,%2};" : "=l"(r) : "f"(x), "f"(y)); return r;
}
__device__ __forceinline__ void unpk2(float& x, float& y, u64 v) {
    asm("mov.b64 {%0,%1}, %2;" : "=f"(x), "=f"(y) : "l"(v));
}
__device__ __forceinline__ u64 f2fma(u64 a, u64 b, u64 c) {
    u64 d; asm("fma.rn.f32x2 %0,%1,%2,%3;" : "=l"(d) : "l"(a), "l"(b), "l"(c)); return d;
}
__device__ __forceinline__ u64 f2mul(u64 a, u64 b) {
    u64 d; asm("mul.rn.f32x2 %0,%1,%2;" : "=l"(d) : "l"(a), "l"(b)); return d;
}

// ---------------- HMMA bf16x3 GEMM: C[M,N] = A[M,K] * W[K,N] ---------------
// CTA 128(M) x 64(N), BK=64, 8 warps (4x2), warp tile 32x32, 2-stage cp.async.
// 96KB smem -> 2 CTAs per SM (the point of this shape).
// A hi/lo [M,K] row-major; W hi/lo [N,K] (pre-transposed).
// MODE 0: plain fp32 store, stride N
// MODE 1: logical N=4096; n0<2048 -> C0 raw, else C1 = silu, both stride 2048
// MODE 2: softplus(v + bias[col]) clipped [1e-3,1e-1], stride N
// MODE 3: logical N=128; n0==0 -> C0, n0==64 -> C1, both stride 64
#define G2_STAGE 49152
#define GEMM_SMEM (2 * G2_STAGE)

template <int MODE>
__global__ __launch_bounds__(256, 2)
void gemm_mma(const bf16* __restrict__ Ah, const bf16* __restrict__ Al,
              const bf16* __restrict__ Bh, const bf16* __restrict__ Bl,
              float* __restrict__ C0, float* __restrict__ C1,
              const float* __restrict__ bias, int M, int N, int K)
{
    extern __shared__ __align__(1024) char smem[];
    const uint32_t su = s2u(smem);
    const int tid = threadIdx.x;
    const int wid = tid >> 5, lane = tid & 31;
    const int wm = wid & 3, wn = wid >> 2;     // 4 x 2 warp grid
    const int n0 = blockIdx.x * 64;
    const int m0 = blockIdx.y * 128;
    const int NT = K >> 6;

    const bf16* srcA[2] = { Ah + (size_t)m0 * K, Al + (size_t)m0 * K };
    const bf16* srcB[2] = { Bh + (size_t)n0 * K, Bl + (size_t)n0 * K };

    auto load_stage = [&](int st, int kc) {
        const uint32_t sbase = su + st * G2_STAGE;
#pragma unroll
        for (int w = 0; w < 2; w++) {           // A hi/lo: 128 rows
            const bf16* g0 = srcA[w] + kc * 64;
#pragma unroll
            for (int i = 0; i < 4; i++) {
                int c = tid + i * 256;
                int row = c >> 3, ch = c & 7;
                CPA16(sbase + w * 16384 + sw128(row * 128 + ch * 16),
                      g0 + (size_t)row * K + ch * 8);
            }
        }
#pragma unroll
        for (int w = 0; w < 2; w++) {           // B hi/lo: 64 rows
            const bf16* g0 = srcB[w] + kc * 64;
#pragma unroll
            for (int i = 0; i < 2; i++) {
                int c = tid + i * 256;
                int row = c >> 3, ch = c & 7;
                CPA16(sbase + 32768 + w * 8192 + sw128(row * 128 + ch * 16),
                      g0 + (size_t)row * K + ch * 8);
            }
        }
        CPA_COMMIT();
    };

    float acc[2][4][4];
#pragma unroll
    for (int a = 0; a < 2; a++)
#pragma unroll
        for (int b = 0; b < 4; b++)
#pragma unroll
            for (int c = 0; c < 4; c++) acc[a][b][c] = 0.f;

    load_stage(0, 0);

    const int arow = lane & 15;
    const int khalf = lane >> 4;

    for (int t = 0; t < NT; ++t) {
        if (t + 1 < NT) { load_stage((t + 1) & 1, t + 1); CPA_WAIT1(); }
        else             CPA_WAIT0();
        __syncthreads();

        const uint32_t sb = su + (t & 1) * G2_STAGE;
#pragma unroll
        for (int kk = 0; kk < 4; kk++) {
            const int kb = kk * 32 + khalf * 16;
            uint32_t aH[2][4], aL[2][4], bHf[2][4], bLf[2][4];
#pragma unroll
            for (int mt = 0; mt < 2; mt++) {
                int r = wm * 32 + mt * 16 + arow;
                ldsm4(aH[mt], sb +         sw128(r * 128 + kb));
                ldsm4(aL[mt], sb + 16384 + sw128(r * 128 + kb));
            }
#pragma unroll
            for (int bt = 0; bt < 2; bt++) {
                int r = wn * 32 + bt * 16 + arow;
                ldsm4(bHf[bt], sb + 32768 + sw128(r * 128 + kb));
                ldsm4(bLf[bt], sb + 40960 + sw128(r * 128 + kb));
            }
#pragma unroll
            for (int mt = 0; mt < 2; mt++)
#pragma unroll
                for (int bt = 0; bt < 2; bt++)
#pragma unroll
                    for (int o = 0; o < 2; o++) {
                        const int j = bt * 2 + o;
                        mma_bf16(acc[mt][j], aH[mt], bHf[bt][o], bHf[bt][o + 2]);
                        mma_bf16(acc[mt][j], aH[mt], bLf[bt][o], bLf[bt][o + 2]);
                        mma_bf16(acc[mt][j], aL[mt], bHf[bt][o], bHf[bt][o + 2]);
                    }
        }
        __syncthreads();
    }

    // ---------------- epilogue from registers -------------------------------
    const int rbase = m0 + wm * 32 + (lane >> 2);
    const int cbase = n0 + wn * 32 + (lane & 3) * 2;
#pragma unroll
    for (int mt = 0; mt < 2; mt++) {
#pragma unroll
        for (int j = 0; j < 4; j++) {
            const int col = cbase + j * 8;
#pragma unroll
            for (int half = 0; half < 2; half++) {
                const int m = rbase + mt * 16 + half * 8;
                float v0 = acc[mt][j][half * 2];
                float v1 = acc[mt][j][half * 2 + 1];
                if (MODE == 0) {
                    *(float2*)(C0 + (size_t)m * N + col) = make_float2(v0, v1);
                } else if (MODE == 1) {
                    if (n0 < 2048)
                        *(float2*)(C0 + (size_t)m * 2048 + col) = make_float2(v0, v1);
                    else
                        *(float2*)(C1 + (size_t)m * 2048 + (col - 2048)) =
                            make_float2(silu_f(v0), silu_f(v1));
                } else if (MODE == 2) {
                    float u0 = v0 + bias[col], u1 = v1 + bias[col + 1];
                    float s0 = (u0 > 15.f) ? u0 : log1pf(__expf(u0));
                    float s1 = (u1 > 15.f) ? u1 : log1pf(__expf(u1));
                    s0 = fminf(fmaxf(s0, 0.001f), 0.1f);
                    s1 = fminf(fmaxf(s1, 0.001f), 0.1f);
                    *(float2*)(C0 + (size_t)m * N + col) = make_float2(s0, s1);
                } else {
                    if (n0 == 0)
                        *(float2*)(C0 + (size_t)m * 64 + col) = make_float2(v0, v1);
                    else
                        *(float2*)(C1 + (size_t)m * 64 + (col - 64)) = make_float2(v0, v1);
                }
            }
        }
    }
}

// ---------------- weight transpose + bf16 hi/lo split -----------------------
__global__ __launch_bounds__(256)
void tsplit_kernel(const float* __restrict__ in, bf16* __restrict__ oh,
                   bf16* __restrict__ ol, int K, int N)
{
    __shared__ float tile[32][33];
    const int n0 = blockIdx.x * 32, k0 = blockIdx.y * 32;
    const int tx = threadIdx.x & 31, ty = threadIdx.x >> 5;
#pragma unroll
    for (int i = 0; i < 4; i++)
        tile[ty + i * 8][tx] = in[(size_t)(k0 + ty + i * 8) * N + n0 + tx];
    __syncthreads();
#pragma unroll
    for (int i = 0; i < 4; i++) {
        float v = tile[tx][ty + i * 8];
        bf16 h = __float2bfloat16(v);
        float lo = v - __bfloat162float(h);
        size_t o = (size_t)(n0 + ty + i * 8) * K + k0 + tx;
        oh[o] = h;
        ol[o] = __float2bfloat16(lo);
    }
}

// ---------------- x split ----------------------------------------------------
__global__ __launch_bounds__(512)
void xsplit_kernel(const float* __restrict__ x, bf16* __restrict__ oh, bf16* __restrict__ ol)
{
    size_t i = (size_t)blockIdx.x * 512 + threadIdx.x;
    float v = x[i];
    bf16 h = __float2bfloat16(v);
    oh[i] = h;
    ol[i] = __float2bfloat16(v - __bfloat162float(h));
}

// ---------------- conv along e, weights indexed by t, + silu + split --------
__global__ __launch_bounds__(256)
void conv_silu_kernel(const float* __restrict__ xz, const float* __restrict__ Wc,
                      float* __restrict__ xc, bf16* __restrict__ xch, bf16* __restrict__ xcl)
{
    __shared__ float s[E_DIM + 4];
    const int row = blockIdx.x;           // b*T + t
    const int t = row & (T_DIM - 1);
    const int tid = threadIdx.x;
    const float* src = xz + (size_t)row * E_DIM;
#pragma unroll
    for (int j = 0; j < E_DIM / 256; ++j)
        s[tid + j * 256 + 1] = src[tid + j * 256];
    if (tid == 0) s[0] = 0.f;
    if (tid < 3) s[E_DIM + 1 + tid] = 0.f;
    __syncthreads();
    const float w0 = Wc[t], w1 = Wc[E_DIM + t], w2 = Wc[2 * E_DIM + t], w3 = Wc[3 * E_DIM + t];
    const size_t base = (size_t)row * E_DIM;
#pragma unroll
    for (int j = 0; j < E_DIM / 256; ++j) {
        int e = tid + j * 256;
        float v = w0 * s[e] + w1 * s[e + 1] + w2 * s[e + 2] + w3 * s[e + 3];
        float sv = silu_f(v);
        xc[base + e] = sv;
        bf16 h = __float2bfloat16(sv);
        xch[base + e] = h;
        xcl[base + e] = __float2bfloat16(sv - __bfloat162float(h));
    }
}

// ---------------- selective scan: warp per (b,e), f32x2 packed, decoupled ---
__global__ __launch_bounds__(512)
void scan_kernel(const float* __restrict__ xc, const float* __restrict__ dt,
                 const float* __restrict__ Bp, const float* __restrict__ Cp,
                 const float* __restrict__ sz, const float* __restrict__ A_log,
                 bf16* __restrict__ ywh, bf16* __restrict__ ywl)
{
    __shared__ float sty[32][17];       // [t mod 32][warp]
    const int tid  = threadIdx.x;
    const int warp = tid >> 5, lane = tid & 31;
    const int e0 = (blockIdx.x & 127) * 16;
    const int b  = blockIdx.x >> 7;
    const int e  = e0 + warp;
    const size_t base   = ((size_t)b * T_DIM) * E_DIM + e;
    const size_t bcbase = ((size_t)b * T_DIM) * N_ST + 2 * lane;

    const float A0 = -__expf(A_log[2 * lane]);
    const float A1 = -__expf(A_log[2 * lane + 1]);
    const u64 A2 = pk2(A0, A1);
    const u64 C24 = pk2(1.f / 24.f, 1.f / 24.f);
    const u64 C6  = pk2(1.f / 6.f, 1.f / 6.f);
    const u64 C05 = pk2(0.5f, 0.5f);
    const u64 C1  = pk2(1.f, 1.f);

    float xv  = xc[base];
    float dtv = dt[base];
    float szv = sz[base];
    float2 Bv = *(const float2*)(Bp + bcbase);
    float2 Cv = *(const float2*)(Cp + bcbase);

    u64 h = 0;
    for (int t = 0; t < T_DIM; ++t) {
        const int tn = (t + 1 < T_DIM) ? (t + 1) : t;
        const float xn  = xc[base + (size_t)tn * E_DIM];
        const float dtn = dt[base + (size_t)tn * E_DIM];
        const float szn = sz[base + (size_t)tn * E_DIM];
        const float2 Bn = *(const float2*)(Bp + bcbase + (size_t)tn * N_ST);
        const float2 Cn = *(const float2*)(Cp + bcbase + (size_t)tn * N_ST);

        const u64 dt2 = pk2(dtv, dtv);
        u64 u = f2mul(dt2, A2);
        u64 r = f2fma(u, C24, C6);
        r = f2fma(u, r, C05);
        r = f2fma(u, r, C1);
        r = f2fma(u, r, C1);
        const float dtx = dtv * xv;
        const u64 dtx2 = pk2(dtx, dtx);
        const u64 Bv2 = pk2(Bv.x, Bv.y);
        const u64 Cv2 = pk2(Cv.x, Cv.y);
        h = f2fma(r, h, f2mul(dtx2, Bv2));
        const u64 yp = f2mul(h, Cv2);
        float y0, y1;
        unpk2(y0, y1, yp);
        float y = y0 + y1;
        y += __shfl_xor_sync(0xFFFFFFFFu, y, 16);
        y += __shfl_xor_sync(0xFFFFFFFFu, y, 8);
        y += __shfl_xor_sync(0xFFFFFFFFu, y, 4);
        y += __shfl_xor_sync(0xFFFFFFFFu, y, 2);
        y += __shfl_xor_sync(0xFFFFFFFFu, y, 1);
        if (lane == 0) sty[t & 31][warp] = y * szv;

        xv = xn; dtv = dtn; szv = szn; Bv = Bn; Cv = Cn;

        if ((t & 31) == 31) {
            __syncthreads();
            const int row = tid >> 4, col = tid & 15;
            const float yv = sty[row][col];
            const bf16 hh = __float2bfloat16(yv);
            const bf16 ll = __float2bfloat16(yv - __bfloat162float(hh));
            const size_t o = ((size_t)b * T_DIM + (t - 31 + row)) * E_DIM + e0 + col;
            ywh[o] = hh;
            ywl[o] = ll;
            __syncthreads();
        }
    }
}

// ---------------------------------------------------------------------------
extern "C" void kernel_launch(void* const* d_in, const int* in_sizes, int n_in,
                              void* d_out, int out_size)
{
    (void)in_sizes; (void)n_in; (void)out_size;
    const float* x      = (const float*)d_in[0];
    const float* W_in   = (const float*)d_in[1];
    const float* W_conv = (const float*)d_in[2];
    const float* W_dt   = (const float*)d_in[3];
    const float* b_dt   = (const float*)d_in[4];
    const float* W_B    = (const float*)d_in[5];
    const float* W_C    = (const float*)d_in[6];
    const float* A_log  = (const float*)d_in[7];
    const float* W_out  = (const float*)d_in[8];
    float* out = (float*)d_out;

    float *xz, *sz, *xc, *dtb, *Bpp, *Cpp;
    bf16 *xh, *xl, *xch, *xcl, *ywh, *ywl;
    bf16 *WinTh, *WinTl, *WdtTh, *WdtTl, *WoutTh, *WoutTl, *WbcH, *WbcL;
    cudaGetSymbolAddress((void**)&xz,  g_xz);
    cudaGetSymbolAddress((void**)&sz,  g_sz);
    cudaGetSymbolAddress((void**)&xc,  g_xc);
    cudaGetSymbolAddress((void**)&dtb, g_dt);
    cudaGetSymbolAddress((void**)&Bpp, g_Bp);
    cudaGetSymbolAddress((void**)&Cpp, g_Cp);
    cudaGetSymbolAddress((void**)&xh,  g_xh);
    cudaGetSymbolAddress((void**)&xl,  g_xl);
    cudaGetSymbolAddress((void**)&xch, g_xch);
    cudaGetSymbolAddress((void**)&xcl, g_xcl);
    cudaGetSymbolAddress((void**)&ywh, g_ywh);
    cudaGetSymbolAddress((void**)&ywl, g_ywl);
    cudaGetSymbolAddress((void**)&WinTh,  g_WinTh);
    cudaGetSymbolAddress((void**)&WinTl,  g_WinTl);
    cudaGetSymbolAddress((void**)&WdtTh,  g_WdtTh);
    cudaGetSymbolAddress((void**)&WdtTl,  g_WdtTl);
    cudaGetSymbolAddress((void**)&WoutTh, g_WoutTh);
    cudaGetSymbolAddress((void**)&WoutTl, g_WoutTl);
    cudaGetSymbolAddress((void**)&WbcH,   g_WbcH);
    cudaGetSymbolAddress((void**)&WbcL,   g_WbcL);

    cudaFuncSetAttribute(gemm_mma<0>, cudaFuncAttributeMaxDynamicSharedMemorySize, GEMM_SMEM);
    cudaFuncSetAttribute(gemm_mma<1>, cudaFuncAttributeMaxDynamicSharedMemorySize, GEMM_SMEM);
    cudaFuncSetAttribute(gemm_mma<2>, cudaFuncAttributeMaxDynamicSharedMemorySize, GEMM_SMEM);
    cudaFuncSetAttribute(gemm_mma<3>, cudaFuncAttributeMaxDynamicSharedMemorySize, GEMM_SMEM);

    // launch order arranged so launch index 5 (ncu -s 5) = dt-projection GEMM
    // 0) x split
    xsplit_kernel<<<(BT_DIM * D_DIM) / 512, 512>>>(x, xh, xl);
    // 1) W_in transpose+split
    tsplit_kernel<<<dim3(4096 / 32, 1024 / 32), 256>>>(W_in, WinTh, WinTl, 1024, 4096);
    // 2) in-projection: [8192,1024] @ [1024,4096] -> xz raw / sz silu
    gemm_mma<1><<<dim3(4096 / 64, BT_DIM / 128), 256, GEMM_SMEM>>>(
        xh, xl, WinTh, WinTl, xz, sz, nullptr, BT_DIM, 4096, 1024);
    // 3) conv along e + silu + bf16 split
    conv_silu_kernel<<<BT_DIM, 256>>>(xz, W_conv, xc, xch, xcl);
    // 4) W_dt transpose+split
    tsplit_kernel<<<dim3(2048 / 32, 2048 / 32), 256>>>(W_dt, WdtTh, WdtTl, 2048, 2048);
    // 5) dt projection + softplus + clip   <-- ncu capture target
    gemm_mma<2><<<dim3(E_DIM / 64, BT_DIM / 128), 256, GEMM_SMEM>>>(
        xch, xcl, WdtTh, WdtTl, dtb, nullptr, b_dt, BT_DIM, E_DIM, E_DIM);
    // 6-7) W_B / W_C splits
    tsplit_kernel<<<dim3(64 / 32, 2048 / 32), 256>>>(W_B, WbcH,             WbcL,             2048, 64);
    tsplit_kernel<<<dim3(64 / 32, 2048 / 32), 256>>>(W_C, WbcH + 64 * 2048, WbcL + 64 * 2048, 2048, 64);
    // 8) B/C projections (one N=128 GEMM, split outputs)
    gemm_mma<3><<<dim3(2, BT_DIM / 128), 256, GEMM_SMEM>>>(
        xch, xcl, WbcH, WbcL, Bpp, Cpp, nullptr, BT_DIM, 128, 2048);
    // 9) W_out split
    tsplit_kernel<<<dim3(1024 / 32, 2048 / 32), 256>>>(W_out, WoutTh, WoutTl, 2048, 1024);
    // 10) selective scan (fuses y * silu(z), emits bf16 hi/lo)
    scan_kernel<<<B_DIM * (E_DIM / 16), 512>>>(xc, dtb, Bpp, Cpp, sz, A_log, ywh, ywl);
    // 11) out projection -> d_out
    gemm_mma<0><<<dim3(D_DIM / 64, BT_DIM / 128), 256, GEMM_SMEM>>>(
        ywh, ywl, WoutTh, WoutTl, out, nullptr, nullptr, BT_DIM, D_DIM, E_DIM);
}

// round 9
// speedup vs baseline: 1.2468x; 1.1531x over previous
#include <cuda_runtime.h>
#include <cuda_fp16.h>
#include <cstdint>

#define E_DIM 2048
#define T_DIM 2048
#define B_DIM 4
#define D_DIM 1024
#define BT_DIM 8192
#define N_ST 64

typedef unsigned long long u64;

// ---------------- scratch (device globals; no allocation allowed) ----------
static __device__ __align__(1024) float g_xz [(size_t)BT_DIM * E_DIM];
static __device__ __align__(1024) float g_sz [(size_t)BT_DIM * E_DIM];
static __device__ __align__(1024) float g_xc [(size_t)BT_DIM * E_DIM];
static __device__ __align__(1024) float g_dt [(size_t)BT_DIM * E_DIM];
static __device__ __align__(1024) float g_Bp [(size_t)BT_DIM * N_ST];
static __device__ __align__(1024) float g_Cp [(size_t)BT_DIM * N_ST];
// fp16 activations (single precision operand; weights carry the split)
static __device__ __align__(1024) __half g_xh  [(size_t)BT_DIM * D_DIM];
static __device__ __align__(1024) __half g_xch [(size_t)BT_DIM * E_DIM];
static __device__ __align__(1024) __half g_ywh [(size_t)BT_DIM * E_DIM];
// fp16 hi/lo transposed weights [N,K]
static __device__ __align__(1024) __half g_WinTh [(size_t)4096 * 1024];
static __device__ __align__(1024) __half g_WinTl [(size_t)4096 * 1024];
static __device__ __align__(1024) __half g_WdtTh [(size_t)2048 * 2048];
static __device__ __align__(1024) __half g_WdtTl [(size_t)2048 * 2048];
static __device__ __align__(1024) __half g_WoutTh[(size_t)1024 * 2048];
static __device__ __align__(1024) __half g_WoutTl[(size_t)1024 * 2048];
static __device__ __align__(1024) __half g_WbcH  [(size_t)128 * 2048];
static __device__ __align__(1024) __half g_WbcL  [(size_t)128 * 2048];

__device__ __forceinline__ float silu_f(float v) { return v / (1.f + __expf(-v)); }

// ---------------- PTX helpers ----------------------------------------------
__device__ __forceinline__ uint32_t s2u(const void* p) {
    uint32_t a;
    asm("{ .reg .u64 t; cvta.to.shared.u64 t, %1; cvt.u32.u64 %0, t; }" : "=r"(a) : "l"(p));
    return a;
}
__device__ __forceinline__ uint32_t sw128(uint32_t off) { return off ^ ((off >> 3) & 0x70); }

#define CPA16(dst, src) asm volatile("cp.async.cg.shared.global [%0], [%1], 16;" :: "r"(dst), "l"(src))
#define CPA_COMMIT()    asm volatile("cp.async.commit_group;" ::: "memory")
#define CPA_WAIT1()     asm volatile("cp.async.wait_group 1;" ::: "memory")
#define CPA_WAIT0()     asm volatile("cp.async.wait_group 0;" ::: "memory")

__device__ __forceinline__ void ldsm4(uint32_t r[4], uint32_t a) {
    asm volatile("ldmatrix.sync.aligned.m8n8.x4.shared.b16 {%0,%1,%2,%3}, [%4];"
        : "=r"(r[0]), "=r"(r[1]), "=r"(r[2]), "=r"(r[3]) : "r"(a));
}
__device__ __forceinline__ void mma_f16(float c[4], const uint32_t a[4],
                                        uint32_t b0, uint32_t b1) {
    asm volatile(
        "mma.sync.aligned.m16n8k16.row.col.f32.f16.f16.f32 "
        "{%0,%1,%2,%3}, {%4,%5,%6,%7}, {%8,%9}, {%0,%1,%2,%3};"
        : "+f"(c[0]), "+f"(c[1]), "+f"(c[2]), "+f"(c[3])
        : "r"(a[0]), "r"(a[1]), "r"(a[2]), "r"(a[3]), "r"(b0), "r"(b1));
}

// packed f32x2
__device__ __forceinline__ u64 pk2(float x, float y) {
    u64 r; asm("mov.b64 %0,{%1,%2};" : "=l"(r) : "f"(x), "f"(y)); return r;
}
__device__ __forceinline__ void unpk2(float& x, float& y, u64 v) {
    asm("mov.b64 {%0,%1}, %2;" : "=f"(x), "=f"(y) : "l"(v));
}
__device__ __forceinline__ u64 f2fma(u64 a, u64 b, u64 c) {
    u64 d; asm("fma.rn.f32x2 %0,%1,%2,%3;" : "=l"(d) : "l"(a), "l"(b), "l"(c)); return d;
}
__device__ __forceinline__ u64 f2mul(u64 a, u64 b) {
    u64 d; asm("mul.rn.f32x2 %0,%1,%2;" : "=l"(d) : "l"(a), "l"(b)); return d;
}

// ---------------- HMMA fp16x2 GEMM: C[M,N] = A[M,K] * W[K,N] ---------------
// A single fp16 [M,K] row-major; W as fp16 hi/lo [N,K] (pre-transposed):
//   C = A*Wh + A*Wl  (weight rounding eliminated; only A rounding remains)
// CTA 128(M) x 64(N), BK=64, 8 warps (4x2), warp tile 32x32, 2-stage cp.async.
// smem/stage: A 16K | Bh 8K | Bl 8K = 32KB; 2 stages = 64KB -> 2+ CTAs/SM.
// MODE 0: plain fp32 store, stride N
// MODE 1: logical N=4096; n0<2048 -> C0 raw, else C1 = silu, both stride 2048
// MODE 2: softplus(v + bias[col]) clipped [1e-3,1e-1], stride N
// MODE 3: logical N=128; n0==0 -> C0, n0==64 -> C1, both stride 64
#define G2_STAGE 32768
#define GEMM_SMEM (2 * G2_STAGE)

template <int MODE>
__global__ __launch_bounds__(256, 2)
void gemm_mma(const __half* __restrict__ Ax, const __half* __restrict__ Bh,
              const __half* __restrict__ Bl,
              float* __restrict__ C0, float* __restrict__ C1,
              const float* __restrict__ bias, int M, int N, int K)
{
    extern __shared__ __align__(1024) char smem[];
    const uint32_t su = s2u(smem);
    const int tid = threadIdx.x;
    const int wid = tid >> 5, lane = tid & 31;
    const int wm = wid & 3, wn = wid >> 2;     // 4 x 2 warp grid
    const int n0 = blockIdx.x * 64;
    const int m0 = blockIdx.y * 128;
    const int NT = K >> 6;

    const __half* srcA = Ax + (size_t)m0 * K;
    const __half* srcB[2] = { Bh + (size_t)n0 * K, Bl + (size_t)n0 * K };

    auto load_stage = [&](int st, int kc) {
        const uint32_t sbase = su + st * G2_STAGE;
        // A: 128 rows x 64 halfs = 16KB
        {
            const __half* g0 = srcA + kc * 64;
#pragma unroll
            for (int i = 0; i < 4; i++) {
                int c = tid + i * 256;
                int row = c >> 3, ch = c & 7;
                CPA16(sbase + sw128(row * 128 + ch * 16),
                      g0 + (size_t)row * K + ch * 8);
            }
        }
        // B hi/lo: 64 rows each = 8KB each
#pragma unroll
        for (int w = 0; w < 2; w++) {
            const __half* g0 = srcB[w] + kc * 64;
#pragma unroll
            for (int i = 0; i < 2; i++) {
                int c = tid + i * 256;
                int row = c >> 3, ch = c & 7;
                CPA16(sbase + 16384 + w * 8192 + sw128(row * 128 + ch * 16),
                      g0 + (size_t)row * K + ch * 8);
            }
        }
        CPA_COMMIT();
    };

    float acc[2][4][4];
#pragma unroll
    for (int a = 0; a < 2; a++)
#pragma unroll
        for (int b = 0; b < 4; b++)
#pragma unroll
            for (int c = 0; c < 4; c++) acc[a][b][c] = 0.f;

    load_stage(0, 0);

    const int arow = lane & 15;
    const int khalf = lane >> 4;

    for (int t = 0; t < NT; ++t) {
        if (t + 1 < NT) { load_stage((t + 1) & 1, t + 1); CPA_WAIT1(); }
        else             CPA_WAIT0();
        __syncthreads();

        const uint32_t sb = su + (t & 1) * G2_STAGE;
#pragma unroll
        for (int kk = 0; kk < 4; kk++) {
            const int kb = kk * 32 + khalf * 16;
            uint32_t aF[2][4], bHf[2][4], bLf[2][4];
#pragma unroll
            for (int mt = 0; mt < 2; mt++) {
                int r = wm * 32 + mt * 16 + arow;
                ldsm4(aF[mt], sb + sw128(r * 128 + kb));
            }
#pragma unroll
            for (int bt = 0; bt < 2; bt++) {
                int r = wn * 32 + bt * 16 + arow;
                ldsm4(bHf[bt], sb + 16384 + sw128(r * 128 + kb));
                ldsm4(bLf[bt], sb + 24576 + sw128(r * 128 + kb));
            }
#pragma unroll
            for (int mt = 0; mt < 2; mt++)
#pragma unroll
                for (int bt = 0; bt < 2; bt++)
#pragma unroll
                    for (int o = 0; o < 2; o++) {
                        const int j = bt * 2 + o;
                        mma_f16(acc[mt][j], aF[mt], bHf[bt][o], bHf[bt][o + 2]);
                        mma_f16(acc[mt][j], aF[mt], bLf[bt][o], bLf[bt][o + 2]);
                    }
        }
        __syncthreads();
    }

    // ---------------- epilogue from registers -------------------------------
    const int rbase = m0 + wm * 32 + (lane >> 2);
    const int cbase = n0 + wn * 32 + (lane & 3) * 2;
#pragma unroll
    for (int mt = 0; mt < 2; mt++) {
#pragma unroll
        for (int j = 0; j < 4; j++) {
            const int col = cbase + j * 8;
#pragma unroll
            for (int half = 0; half < 2; half++) {
                const int m = rbase + mt * 16 + half * 8;
                float v0 = acc[mt][j][half * 2];
                float v1 = acc[mt][j][half * 2 + 1];
                if (MODE == 0) {
                    *(float2*)(C0 + (size_t)m * N + col) = make_float2(v0, v1);
                } else if (MODE == 1) {
                    if (n0 < 2048)
                        *(float2*)(C0 + (size_t)m * 2048 + col) = make_float2(v0, v1);
                    else
                        *(float2*)(C1 + (size_t)m * 2048 + (col - 2048)) =
                            make_float2(silu_f(v0), silu_f(v1));
                } else if (MODE == 2) {
                    float u0 = v0 + bias[col], u1 = v1 + bias[col + 1];
                    float s0 = (u0 > 15.f) ? u0 : log1pf(__expf(u0));
                    float s1 = (u1 > 15.f) ? u1 : log1pf(__expf(u1));
                    s0 = fminf(fmaxf(s0, 0.001f), 0.1f);
                    s1 = fminf(fmaxf(s1, 0.001f), 0.1f);
                    *(float2*)(C0 + (size_t)m * N + col) = make_float2(s0, s1);
                } else {
                    if (n0 == 0)
                        *(float2*)(C0 + (size_t)m * 64 + col) = make_float2(v0, v1);
                    else
                        *(float2*)(C1 + (size_t)m * 64 + (col - 64)) = make_float2(v0, v1);
                }
            }
        }
    }
}

// ---------------- weight transpose + fp16 hi/lo split -----------------------
// in: [K,N] fp32 -> out hi/lo [N,K] fp16 (W = Wh + Wl to ~1e-6 relative)
__global__ __launch_bounds__(256)
void tsplit_kernel(const float* __restrict__ in, __half* __restrict__ oh,
                   __half* __restrict__ ol, int K, int N)
{
    __shared__ float tile[32][33];
    const int n0 = blockIdx.x * 32, k0 = blockIdx.y * 32;
    const int tx = threadIdx.x & 31, ty = threadIdx.x >> 5;
#pragma unroll
    for (int i = 0; i < 4; i++)
        tile[ty + i * 8][tx] = in[(size_t)(k0 + ty + i * 8) * N + n0 + tx];
    __syncthreads();
#pragma unroll
    for (int i = 0; i < 4; i++) {
        float v = tile[tx][ty + i * 8];
        __half h = __float2half(v);
        float lo = v - __half2float(h);
        size_t o = (size_t)(n0 + ty + i * 8) * K + k0 + tx;
        oh[o] = h;
        ol[o] = __float2half(lo);
    }
}

// ---------------- x -> fp16 --------------------------------------------------
__global__ __launch_bounds__(512)
void xcvt_kernel(const float* __restrict__ x, __half* __restrict__ oh)
{
    size_t i = (size_t)blockIdx.x * 512 + threadIdx.x;
    oh[i] = __float2half(x[i]);
}

// ---------------- conv along e, weights indexed by t, + silu ----------------
__global__ __launch_bounds__(256)
void conv_silu_kernel(const float* __restrict__ xz, const float* __restrict__ Wc,
                      float* __restrict__ xc, __half* __restrict__ xch)
{
    __shared__ float s[E_DIM + 4];
    const int row = blockIdx.x;           // b*T + t
    const int t = row & (T_DIM - 1);
    const int tid = threadIdx.x;
    const float* src = xz + (size_t)row * E_DIM;
#pragma unroll
    for (int j = 0; j < E_DIM / 256; ++j)
        s[tid + j * 256 + 1] = src[tid + j * 256];
    if (tid == 0) s[0] = 0.f;
    if (tid < 3) s[E_DIM + 1 + tid] = 0.f;
    __syncthreads();
    const float w0 = Wc[t], w1 = Wc[E_DIM + t], w2 = Wc[2 * E_DIM + t], w3 = Wc[3 * E_DIM + t];
    const size_t base = (size_t)row * E_DIM;
#pragma unroll
    for (int j = 0; j < E_DIM / 256; ++j) {
        int e = tid + j * 256;
        float v = w0 * s[e] + w1 * s[e + 1] + w2 * s[e + 2] + w3 * s[e + 3];
        float sv = silu_f(v);
        xc[base + e] = sv;
        xch[base + e] = __float2half(sv);
    }
}

// ---------------- selective scan: warp per (b,e), f32x2 packed, decoupled ---
__global__ __launch_bounds__(512)
void scan_kernel(const float* __restrict__ xc, const float* __restrict__ dt,
                 const float* __restrict__ Bp, const float* __restrict__ Cp,
                 const float* __restrict__ sz, const float* __restrict__ A_log,
                 __half* __restrict__ yw)
{
    __shared__ float sty[32][17];       // [t mod 32][warp]
    const int tid  = threadIdx.x;
    const int warp = tid >> 5, lane = tid & 31;
    const int e0 = (blockIdx.x & 127) * 16;
    const int b  = blockIdx.x >> 7;
    const int e  = e0 + warp;
    const size_t base   = ((size_t)b * T_DIM) * E_DIM + e;
    const size_t bcbase = ((size_t)b * T_DIM) * N_ST + 2 * lane;

    const float A0 = -__expf(A_log[2 * lane]);
    const float A1 = -__expf(A_log[2 * lane + 1]);
    const u64 A2 = pk2(A0, A1);
    const u64 C24 = pk2(1.f / 24.f, 1.f / 24.f);
    const u64 C6  = pk2(1.f / 6.f, 1.f / 6.f);
    const u64 C05 = pk2(0.5f, 0.5f);
    const u64 C1  = pk2(1.f, 1.f);

    float xv  = xc[base];
    float dtv = dt[base];
    float szv = sz[base];
    float2 Bv = *(const float2*)(Bp + bcbase);
    float2 Cv = *(const float2*)(Cp + bcbase);

    u64 h = 0;
    for (int t = 0; t < T_DIM; ++t) {
        const int tn = (t + 1 < T_DIM) ? (t + 1) : t;
        const float xn  = xc[base + (size_t)tn * E_DIM];
        const float dtn = dt[base + (size_t)tn * E_DIM];
        const float szn = sz[base + (size_t)tn * E_DIM];
        const float2 Bn = *(const float2*)(Bp + bcbase + (size_t)tn * N_ST);
        const float2 Cn = *(const float2*)(Cp + bcbase + (size_t)tn * N_ST);

        const u64 dt2 = pk2(dtv, dtv);
        u64 u = f2mul(dt2, A2);
        u64 r = f2fma(u, C24, C6);
        r = f2fma(u, r, C05);
        r = f2fma(u, r, C1);
        r = f2fma(u, r, C1);
        const float dtx = dtv * xv;
        const u64 dtx2 = pk2(dtx, dtx);
        const u64 Bv2 = pk2(Bv.x, Bv.y);
        const u64 Cv2 = pk2(Cv.x, Cv.y);
        h = f2fma(r, h, f2mul(dtx2, Bv2));
        const u64 yp = f2mul(h, Cv2);
        float y0, y1;
        unpk2(y0, y1, yp);
        float y = y0 + y1;
        y += __shfl_xor_sync(0xFFFFFFFFu, y, 16);
        y += __shfl_xor_sync(0xFFFFFFFFu, y, 8);
        y += __shfl_xor_sync(0xFFFFFFFFu, y, 4);
        y += __shfl_xor_sync(0xFFFFFFFFu, y, 2);
        y += __shfl_xor_sync(0xFFFFFFFFu, y, 1);
        if (lane == 0) sty[t & 31][warp] = y * szv;

        xv = xn; dtv = dtn; szv = szn; Bv = Bn; Cv = Cn;

        if ((t & 31) == 31) {
            __syncthreads();
            const int row = tid >> 4, col = tid & 15;
            const float yv = sty[row][col];
            const size_t o = ((size_t)b * T_DIM + (t - 31 + row)) * E_DIM + e0 + col;
            yw[o] = __float2half(yv);
            __syncthreads();
        }
    }
}

// ---------------------------------------------------------------------------
extern "C" void kernel_launch(void* const* d_in, const int* in_sizes, int n_in,
                              void* d_out, int out_size)
{
    (void)in_sizes; (void)n_in; (void)out_size;
    const float* x      = (const float*)d_in[0];
    const float* W_in   = (const float*)d_in[1];
    const float* W_conv = (const float*)d_in[2];
    const float* W_dt   = (const float*)d_in[3];
    const float* b_dt   = (const float*)d_in[4];
    const float* W_B    = (const float*)d_in[5];
    const float* W_C    = (const float*)d_in[6];
    const float* A_log  = (const float*)d_in[7];
    const float* W_out  = (const float*)d_in[8];
    float* out = (float*)d_out;

    float *xz, *sz, *xc, *dtb, *Bpp, *Cpp;
    __half *xh, *xch, *ywh;
    __half *WinTh, *WinTl, *WdtTh, *WdtTl, *WoutTh, *WoutTl, *WbcH, *WbcL;
    cudaGetSymbolAddress((void**)&xz,  g_xz);
    cudaGetSymbolAddress((void**)&sz,  g_sz);
    cudaGetSymbolAddress((void**)&xc,  g_xc);
    cudaGetSymbolAddress((void**)&dtb, g_dt);
    cudaGetSymbolAddress((void**)&Bpp, g_Bp);
    cudaGetSymbolAddress((void**)&Cpp, g_Cp);
    cudaGetSymbolAddress((void**)&xh,  g_xh);
    cudaGetSymbolAddress((void**)&xch, g_xch);
    cudaGetSymbolAddress((void**)&ywh, g_ywh);
    cudaGetSymbolAddress((void**)&WinTh,  g_WinTh);
    cudaGetSymbolAddress((void**)&WinTl,  g_WinTl);
    cudaGetSymbolAddress((void**)&WdtTh,  g_WdtTh);
    cudaGetSymbolAddress((void**)&WdtTl,  g_WdtTl);
    cudaGetSymbolAddress((void**)&WoutTh, g_WoutTh);
    cudaGetSymbolAddress((void**)&WoutTl, g_WoutTl);
    cudaGetSymbolAddress((void**)&WbcH,   g_WbcH);
    cudaGetSymbolAddress((void**)&WbcL,   g_WbcL);

    cudaFuncSetAttribute(gemm_mma<0>, cudaFuncAttributeMaxDynamicSharedMemorySize, GEMM_SMEM);
    cudaFuncSetAttribute(gemm_mma<1>, cudaFuncAttributeMaxDynamicSharedMemorySize, GEMM_SMEM);
    cudaFuncSetAttribute(gemm_mma<2>, cudaFuncAttributeMaxDynamicSharedMemorySize, GEMM_SMEM);
    cudaFuncSetAttribute(gemm_mma<3>, cudaFuncAttributeMaxDynamicSharedMemorySize, GEMM_SMEM);

    // 0) x -> fp16
    xcvt_kernel<<<(BT_DIM * D_DIM) / 512, 512>>>(x, xh);
    // 1) W_in transpose+split
    tsplit_kernel<<<dim3(4096 / 32, 1024 / 32), 256>>>(W_in, WinTh, WinTl, 1024, 4096);
    // 2) in-projection: [8192,1024] @ [1024,4096] -> xz raw / sz silu
    gemm_mma<1><<<dim3(4096 / 64, BT_DIM / 128), 256, GEMM_SMEM>>>(
        xh, WinTh, WinTl, xz, sz, nullptr, BT_DIM, 4096, 1024);
    // 3) conv along e + silu (+ fp16 copy)
    conv_silu_kernel<<<BT_DIM, 256>>>(xz, W_conv, xc, xch);
    // 4) W_dt transpose+split
    tsplit_kernel<<<dim3(2048 / 32, 2048 / 32), 256>>>(W_dt, WdtTh, WdtTl, 2048, 2048);
    // 5) dt projection + softplus + clip   <-- ncu capture target
    gemm_mma<2><<<dim3(E_DIM / 64, BT_DIM / 128), 256, GEMM_SMEM>>>(
        xch, WdtTh, WdtTl, dtb, nullptr, b_dt, BT_DIM, E_DIM, E_DIM);
    // 6-7) W_B / W_C splits
    tsplit_kernel<<<dim3(64 / 32, 2048 / 32), 256>>>(W_B, WbcH,             WbcL,             2048, 64);
    tsplit_kernel<<<dim3(64 / 32, 2048 / 32), 256>>>(W_C, WbcH + 64 * 2048, WbcL + 64 * 2048, 2048, 64);
    // 8) B/C projections (one logical N=128 GEMM, split outputs)
    gemm_mma<3><<<dim3(2, BT_DIM / 128), 256, GEMM_SMEM>>>(
        xch, WbcH, WbcL, Bpp, Cpp, nullptr, BT_DIM, 128, 2048);
    // 9) W_out split
    tsplit_kernel<<<dim3(1024 / 32, 2048 / 32), 256>>>(W_out, WoutTh, WoutTl, 2048, 1024);
    // 10) selective scan (fuses y * silu(z), emits fp16)
    scan_kernel<<<B_DIM * (E_DIM / 16), 512>>>(xc, dtb, Bpp, Cpp, sz, A_log, ywh);
    // 11) out projection -> d_out
    gemm_mma<0><<<dim3(D_DIM / 64, BT_DIM / 128), 256, GEMM_SMEM>>>(
        ywh, WoutTh, WoutTl, out, nullptr, nullptr, BT_DIM, D_DIM, E_DIM);
}

// round 10
// speedup vs baseline: 1.3040x; 1.0459x over previous
#include <cuda_runtime.h>
#include <cuda_fp16.h>
#include <cstdint>

#define E_DIM 2048
#define T_DIM 2048
#define B_DIM 4
#define D_DIM 1024
#define BT_DIM 8192
#define N_ST 64

typedef unsigned long long u64;

// ---------------- scratch (device globals; no allocation allowed) ----------
static __device__ __align__(1024) float g_xz [(size_t)BT_DIM * E_DIM];
static __device__ __align__(1024) float g_sz [(size_t)BT_DIM * E_DIM];
static __device__ __align__(1024) float g_xc [(size_t)BT_DIM * E_DIM];
static __device__ __align__(1024) float g_dt [(size_t)BT_DIM * E_DIM];
static __device__ __align__(1024) float g_Bp [(size_t)BT_DIM * N_ST];
static __device__ __align__(1024) float g_Cp [(size_t)BT_DIM * N_ST];
// fp16 activations (single operand; weights carry the split where kept)
static __device__ __align__(1024) __half g_xh  [(size_t)BT_DIM * D_DIM];
static __device__ __align__(1024) __half g_xch [(size_t)BT_DIM * E_DIM];
static __device__ __align__(1024) __half g_ywh [(size_t)BT_DIM * E_DIM];
// fp16 hi/lo transposed weights [N,K]
static __device__ __align__(1024) __half g_WinTh [(size_t)4096 * 1024];
static __device__ __align__(1024) __half g_WinTl [(size_t)4096 * 1024];
static __device__ __align__(1024) __half g_WdtTh [(size_t)2048 * 2048];
static __device__ __align__(1024) __half g_WoutTh[(size_t)1024 * 2048];
static __device__ __align__(1024) __half g_WoutTl[(size_t)1024 * 2048];
static __device__ __align__(1024) __half g_WbcH  [(size_t)128 * 2048];
static __device__ __align__(1024) __half g_WbcL  [(size_t)128 * 2048];

__device__ __forceinline__ float silu_f(float v) { return v / (1.f + __expf(-v)); }

// ---------------- PTX helpers ----------------------------------------------
__device__ __forceinline__ uint32_t s2u(const void* p) {
    uint32_t a;
    asm("{ .reg .u64 t; cvta.to.shared.u64 t, %1; cvt.u32.u64 %0, t; }" : "=r"(a) : "l"(p));
    return a;
}
__device__ __forceinline__ uint32_t sw128(uint32_t off) { return off ^ ((off >> 3) & 0x70); }

#define CPA16(dst, src) asm volatile("cp.async.cg.shared.global [%0], [%1], 16;" :: "r"(dst), "l"(src))
#define CPA_COMMIT()    asm volatile("cp.async.commit_group;" ::: "memory")
#define CPA_WAIT1()     asm volatile("cp.async.wait_group 1;" ::: "memory")
#define CPA_WAIT0()     asm volatile("cp.async.wait_group 0;" ::: "memory")

__device__ __forceinline__ void ldsm4(uint32_t r[4], uint32_t a) {
    asm volatile("ldmatrix.sync.aligned.m8n8.x4.shared.b16 {%0,%1,%2,%3}, [%4];"
        : "=r"(r[0]), "=r"(r[1]), "=r"(r[2]), "=r"(r[3]) : "r"(a));
}
__device__ __forceinline__ void mma_f16(float c[4], const uint32_t a[4],
                                        uint32_t b0, uint32_t b1) {
    asm volatile(
        "mma.sync.aligned.m16n8k16.row.col.f32.f16.f16.f32 "
        "{%0,%1,%2,%3}, {%4,%5,%6,%7}, {%8,%9}, {%0,%1,%2,%3};"
        : "+f"(c[0]), "+f"(c[1]), "+f"(c[2]), "+f"(c[3])
        : "r"(a[0]), "r"(a[1]), "r"(a[2]), "r"(a[3]), "r"(b0), "r"(b1));
}

// packed f32x2
__device__ __forceinline__ u64 pk2(float x, float y) {
    u64 r; asm("mov.b64 %0,{%1,%2};" : "=l"(r) : "f"(x), "f"(y)); return r;
}
__device__ __forceinline__ void unpk2(float& x, float& y, u64 v) {
    asm("mov.b64 {%0,%1}, %2;" : "=f"(x), "=f"(y) : "l"(v));
}
__device__ __forceinline__ u64 f2fma(u64 a, u64 b, u64 c) {
    u64 d; asm("fma.rn.f32x2 %0,%1,%2,%3;" : "=l"(d) : "l"(a), "l"(b), "l"(c)); return d;
}
__device__ __forceinline__ u64 f2mul(u64 a, u64 b) {
    u64 d; asm("mul.rn.f32x2 %0,%1,%2;" : "=l"(d) : "l"(a), "l"(b)); return d;
}

// ---------------- HMMA fp16 GEMM: C[M,N] = A[M,K] * W[K,N] -----------------
// A single fp16 [M,K]; W fp16 hi (+ optional lo) [N,K] pre-transposed.
// CTA 128(M) x 64(N), BK=64, 8 warps (4x2), warp tile 32x32, 2-stage cp.async.
// SPLIT selects whether the Wl term is applied; for MODE 1 the Wl term is
// applied ONLY to the x-half (n0 < 2048) -- the z gate tolerates fp16 weights.
// MODE 0: plain fp32 store, stride N
// MODE 1: logical N=4096; n0<2048 -> C0 raw (split), else C1 = silu (no split)
// MODE 2: softplus(v + bias[col]) clipped [1e-3,1e-1], stride N
// MODE 3: logical N=128; n0==0 -> C0, n0==64 -> C1, both stride 64
#define G2_STAGE 32768
#define GEMM_SMEM (2 * G2_STAGE)

template <int MODE, bool SPLIT>
__global__ __launch_bounds__(256, 2)
void gemm_mma(const __half* __restrict__ Ax, const __half* __restrict__ Bh,
              const __half* __restrict__ Bl,
              float* __restrict__ C0, float* __restrict__ C1,
              const float* __restrict__ bias, int M, int N, int K)
{
    extern __shared__ __align__(1024) char smem[];
    const uint32_t su = s2u(smem);
    const int tid = threadIdx.x;
    const int wid = tid >> 5, lane = tid & 31;
    const int wm = wid & 3, wn = wid >> 2;     // 4 x 2 warp grid
    const int n0 = blockIdx.x * 64;
    const int m0 = blockIdx.y * 128;
    const int NT = K >> 6;
    // Wl term active? (uniform per CTA)
    const bool lo_on = SPLIT && (MODE != 1 || n0 < 2048);

    const __half* srcA = Ax + (size_t)m0 * K;
    const __half* srcBh = Bh + (size_t)n0 * K;
    const __half* srcBl = Bl ? (Bl + (size_t)n0 * K) : nullptr;

    auto load_stage = [&](int st, int kc) {
        const uint32_t sbase = su + st * G2_STAGE;
        {   // A: 128 rows x 64 halfs = 16KB
            const __half* g0 = srcA + kc * 64;
#pragma unroll
            for (int i = 0; i < 4; i++) {
                int c = tid + i * 256;
                int row = c >> 3, ch = c & 7;
                CPA16(sbase + sw128(row * 128 + ch * 16),
                      g0 + (size_t)row * K + ch * 8);
            }
        }
        {   // B hi: 64 rows = 8KB
            const __half* g0 = srcBh + kc * 64;
#pragma unroll
            for (int i = 0; i < 2; i++) {
                int c = tid + i * 256;
                int row = c >> 3, ch = c & 7;
                CPA16(sbase + 16384 + sw128(row * 128 + ch * 16),
                      g0 + (size_t)row * K + ch * 8);
            }
        }
        if (lo_on) {   // B lo: 64 rows = 8KB
            const __half* g0 = srcBl + kc * 64;
#pragma unroll
            for (int i = 0; i < 2; i++) {
                int c = tid + i * 256;
                int row = c >> 3, ch = c & 7;
                CPA16(sbase + 24576 + sw128(row * 128 + ch * 16),
                      g0 + (size_t)row * K + ch * 8);
            }
        }
        CPA_COMMIT();
    };

    float acc[2][4][4];
#pragma unroll
    for (int a = 0; a < 2; a++)
#pragma unroll
        for (int b = 0; b < 4; b++)
#pragma unroll
            for (int c = 0; c < 4; c++) acc[a][b][c] = 0.f;

    load_stage(0, 0);

    const int arow = lane & 15;
    const int khalf = lane >> 4;

    for (int t = 0; t < NT; ++t) {
        if (t + 1 < NT) { load_stage((t + 1) & 1, t + 1); CPA_WAIT1(); }
        else             CPA_WAIT0();
        __syncthreads();

        const uint32_t sb = su + (t & 1) * G2_STAGE;
#pragma unroll
        for (int kk = 0; kk < 4; kk++) {
            const int kb = kk * 32 + khalf * 16;
            uint32_t aF[2][4], bHf[2][4], bLf[2][4];
#pragma unroll
            for (int mt = 0; mt < 2; mt++) {
                int r = wm * 32 + mt * 16 + arow;
                ldsm4(aF[mt], sb + sw128(r * 128 + kb));
            }
#pragma unroll
            for (int bt = 0; bt < 2; bt++) {
                int r = wn * 32 + bt * 16 + arow;
                ldsm4(bHf[bt], sb + 16384 + sw128(r * 128 + kb));
            }
            if (lo_on) {
#pragma unroll
                for (int bt = 0; bt < 2; bt++) {
                    int r = wn * 32 + bt * 16 + arow;
                    ldsm4(bLf[bt], sb + 24576 + sw128(r * 128 + kb));
                }
            }
#pragma unroll
            for (int mt = 0; mt < 2; mt++)
#pragma unroll
                for (int bt = 0; bt < 2; bt++)
#pragma unroll
                    for (int o = 0; o < 2; o++) {
                        const int j = bt * 2 + o;
                        mma_f16(acc[mt][j], aF[mt], bHf[bt][o], bHf[bt][o + 2]);
                        if (lo_on)
                            mma_f16(acc[mt][j], aF[mt], bLf[bt][o], bLf[bt][o + 2]);
                    }
        }
        __syncthreads();
    }

    // ---------------- epilogue from registers -------------------------------
    const int rbase = m0 + wm * 32 + (lane >> 2);
    const int cbase = n0 + wn * 32 + (lane & 3) * 2;
#pragma unroll
    for (int mt = 0; mt < 2; mt++) {
#pragma unroll
        for (int j = 0; j < 4; j++) {
            const int col = cbase + j * 8;
#pragma unroll
            for (int half = 0; half < 2; half++) {
                const int m = rbase + mt * 16 + half * 8;
                float v0 = acc[mt][j][half * 2];
                float v1 = acc[mt][j][half * 2 + 1];
                if (MODE == 0) {
                    *(float2*)(C0 + (size_t)m * N + col) = make_float2(v0, v1);
                } else if (MODE == 1) {
                    if (n0 < 2048)
                        *(float2*)(C0 + (size_t)m * 2048 + col) = make_float2(v0, v1);
                    else
                        *(float2*)(C1 + (size_t)m * 2048 + (col - 2048)) =
                            make_float2(silu_f(v0), silu_f(v1));
                } else if (MODE == 2) {
                    float u0 = v0 + bias[col], u1 = v1 + bias[col + 1];
                    float s0 = (u0 > 15.f) ? u0 : log1pf(__expf(u0));
                    float s1 = (u1 > 15.f) ? u1 : log1pf(__expf(u1));
                    s0 = fminf(fmaxf(s0, 0.001f), 0.1f);
                    s1 = fminf(fmaxf(s1, 0.001f), 0.1f);
                    *(float2*)(C0 + (size_t)m * N + col) = make_float2(s0, s1);
                } else {
                    if (n0 == 0)
                        *(float2*)(C0 + (size_t)m * 64 + col) = make_float2(v0, v1);
                    else
                        *(float2*)(C1 + (size_t)m * 64 + (col - 64)) = make_float2(v0, v1);
                }
            }
        }
    }
}

// ---------------- weight transpose + fp16 hi/lo split -----------------------
// in: [K,N] fp32 -> out hi (+ optional lo) [N,K] fp16
__global__ __launch_bounds__(256)
void tsplit_kernel(const float* __restrict__ in, __half* __restrict__ oh,
                   __half* __restrict__ ol, int K, int N)
{
    __shared__ float tile[32][33];
    const int n0 = blockIdx.x * 32, k0 = blockIdx.y * 32;
    const int tx = threadIdx.x & 31, ty = threadIdx.x >> 5;
#pragma unroll
    for (int i = 0; i < 4; i++)
        tile[ty + i * 8][tx] = in[(size_t)(k0 + ty + i * 8) * N + n0 + tx];
    __syncthreads();
#pragma unroll
    for (int i = 0; i < 4; i++) {
        float v = tile[tx][ty + i * 8];
        __half h = __float2half(v);
        size_t o = (size_t)(n0 + ty + i * 8) * K + k0 + tx;
        oh[o] = h;
        if (ol) ol[o] = __float2half(v - __half2float(h));
    }
}

// ---------------- x -> fp16 --------------------------------------------------
__global__ __launch_bounds__(512)
void xcvt_kernel(const float* __restrict__ x, __half* __restrict__ oh)
{
    size_t i = (size_t)blockIdx.x * 512 + threadIdx.x;
    oh[i] = __float2half(x[i]);
}

// ---------------- conv along e, weights indexed by t, + silu ----------------
__global__ __launch_bounds__(256)
void conv_silu_kernel(const float* __restrict__ xz, const float* __restrict__ Wc,
                      float* __restrict__ xc, __half* __restrict__ xch)
{
    __shared__ float s[E_DIM + 4];
    const int row = blockIdx.x;           // b*T + t
    const int t = row & (T_DIM - 1);
    const int tid = threadIdx.x;
    const float* src = xz + (size_t)row * E_DIM;
#pragma unroll
    for (int j = 0; j < E_DIM / 256; ++j)
        s[tid + j * 256 + 1] = src[tid + j * 256];
    if (tid == 0) s[0] = 0.f;
    if (tid < 3) s[E_DIM + 1 + tid] = 0.f;
    __syncthreads();
    const float w0 = Wc[t], w1 = Wc[E_DIM + t], w2 = Wc[2 * E_DIM + t], w3 = Wc[3 * E_DIM + t];
    const size_t base = (size_t)row * E_DIM;
#pragma unroll
    for (int j = 0; j < E_DIM / 256; ++j) {
        int e = tid + j * 256;
        float v = w0 * s[e] + w1 * s[e + 1] + w2 * s[e + 2] + w3 * s[e + 3];
        float sv = silu_f(v);
        xc[base + e] = sv;
        xch[base + e] = __float2half(sv);
    }
}

// ---------------- selective scan: warp per (b,e), f32x2 packed, decoupled ---
__global__ __launch_bounds__(512)
void scan_kernel(const float* __restrict__ xc, const float* __restrict__ dt,
                 const float* __restrict__ Bp, const float* __restrict__ Cp,
                 const float* __restrict__ sz, const float* __restrict__ A_log,
                 __half* __restrict__ yw)
{
    __shared__ float sty[32][17];       // [t mod 32][warp]
    const int tid  = threadIdx.x;
    const int warp = tid >> 5, lane = tid & 31;
    const int e0 = (blockIdx.x & 127) * 16;
    const int b  = blockIdx.x >> 7;
    const int e  = e0 + warp;
    const size_t base   = ((size_t)b * T_DIM) * E_DIM + e;
    const size_t bcbase = ((size_t)b * T_DIM) * N_ST + 2 * lane;

    const float A0 = -__expf(A_log[2 * lane]);
    const float A1 = -__expf(A_log[2 * lane + 1]);
    const u64 A2 = pk2(A0, A1);
    const u64 C24 = pk2(1.f / 24.f, 1.f / 24.f);
    const u64 C6  = pk2(1.f / 6.f, 1.f / 6.f);
    const u64 C05 = pk2(0.5f, 0.5f);
    const u64 C1  = pk2(1.f, 1.f);

    float xv  = xc[base];
    float dtv = dt[base];
    float szv = sz[base];
    float2 Bv = *(const float2*)(Bp + bcbase);
    float2 Cv = *(const float2*)(Cp + bcbase);

    u64 h = 0;
    for (int t = 0; t < T_DIM; ++t) {
        const int tn = (t + 1 < T_DIM) ? (t + 1) : t;
        const float xn  = xc[base + (size_t)tn * E_DIM];
        const float dtn = dt[base + (size_t)tn * E_DIM];
        const float szn = sz[base + (size_t)tn * E_DIM];
        const float2 Bn = *(const float2*)(Bp + bcbase + (size_t)tn * N_ST);
        const float2 Cn = *(const float2*)(Cp + bcbase + (size_t)tn * N_ST);

        const u64 dt2 = pk2(dtv, dtv);
        u64 u = f2mul(dt2, A2);
        u64 r = f2fma(u, C24, C6);
        r = f2fma(u, r, C05);
        r = f2fma(u, r, C1);
        r = f2fma(u, r, C1);
        const float dtx = dtv * xv;
        const u64 dtx2 = pk2(dtx, dtx);
        const u64 Bv2 = pk2(Bv.x, Bv.y);
        const u64 Cv2 = pk2(Cv.x, Cv.y);
        h = f2fma(r, h, f2mul(dtx2, Bv2));
        const u64 yp = f2mul(h, Cv2);
        float y0, y1;
        unpk2(y0, y1, yp);
        float y = y0 + y1;
        y += __shfl_xor_sync(0xFFFFFFFFu, y, 16);
        y += __shfl_xor_sync(0xFFFFFFFFu, y, 8);
        y += __shfl_xor_sync(0xFFFFFFFFu, y, 4);
        y += __shfl_xor_sync(0xFFFFFFFFu, y, 2);
        y += __shfl_xor_sync(0xFFFFFFFFu, y, 1);
        if (lane == 0) sty[t & 31][warp] = y * szv;

        xv = xn; dtv = dtn; szv = szn; Bv = Bn; Cv = Cn;

        if ((t & 31) == 31) {
            __syncthreads();
            const int row = tid >> 4, col = tid & 15;
            const float yv = sty[row][col];
            const size_t o = ((size_t)b * T_DIM + (t - 31 + row)) * E_DIM + e0 + col;
            yw[o] = __float2half(yv);
            __syncthreads();
        }
    }
}

// ---------------------------------------------------------------------------
extern "C" void kernel_launch(void* const* d_in, const int* in_sizes, int n_in,
                              void* d_out, int out_size)
{
    (void)in_sizes; (void)n_in; (void)out_size;
    const float* x      = (const float*)d_in[0];
    const float* W_in   = (const float*)d_in[1];
    const float* W_conv = (const float*)d_in[2];
    const float* W_dt   = (const float*)d_in[3];
    const float* b_dt   = (const float*)d_in[4];
    const float* W_B    = (const float*)d_in[5];
    const float* W_C    = (const float*)d_in[6];
    const float* A_log  = (const float*)d_in[7];
    const float* W_out  = (const float*)d_in[8];
    float* out = (float*)d_out;

    float *xz, *sz, *xc, *dtb, *Bpp, *Cpp;
    __half *xh, *xch, *ywh;
    __half *WinTh, *WinTl, *WdtTh, *WoutTh, *WoutTl, *WbcH, *WbcL;
    cudaGetSymbolAddress((void**)&xz,  g_xz);
    cudaGetSymbolAddress((void**)&sz,  g_sz);
    cudaGetSymbolAddress((void**)&xc,  g_xc);
    cudaGetSymbolAddress((void**)&dtb, g_dt);
    cudaGetSymbolAddress((void**)&Bpp, g_Bp);
    cudaGetSymbolAddress((void**)&Cpp, g_Cp);
    cudaGetSymbolAddress((void**)&xh,  g_xh);
    cudaGetSymbolAddress((void**)&xch, g_xch);
    cudaGetSymbolAddress((void**)&ywh, g_ywh);
    cudaGetSymbolAddress((void**)&WinTh,  g_WinTh);
    cudaGetSymbolAddress((void**)&WinTl,  g_WinTl);
    cudaGetSymbolAddress((void**)&WdtTh,  g_WdtTh);
    cudaGetSymbolAddress((void**)&WoutTh, g_WoutTh);
    cudaGetSymbolAddress((void**)&WoutTl, g_WoutTl);
    cudaGetSymbolAddress((void**)&WbcH,   g_WbcH);
    cudaGetSymbolAddress((void**)&WbcL,   g_WbcL);

    cudaFuncSetAttribute((const void*)gemm_mma<0, true>,  cudaFuncAttributeMaxDynamicSharedMemorySize, GEMM_SMEM);
    cudaFuncSetAttribute((const void*)gemm_mma<1, true>,  cudaFuncAttributeMaxDynamicSharedMemorySize, GEMM_SMEM);
    cudaFuncSetAttribute((const void*)gemm_mma<2, false>, cudaFuncAttributeMaxDynamicSharedMemorySize, GEMM_SMEM);
    cudaFuncSetAttribute((const void*)gemm_mma<3, true>,  cudaFuncAttributeMaxDynamicSharedMemorySize, GEMM_SMEM);

    // 0) x -> fp16
    xcvt_kernel<<<(BT_DIM * D_DIM) / 512, 512>>>(x, xh);
    // 1) W_in transpose+split
    tsplit_kernel<<<dim3(4096 / 32, 1024 / 32), 256>>>(W_in, WinTh, WinTl, 1024, 4096);
    // 2) in-projection: x-half split, z-half single-term + silu
    gemm_mma<1, true><<<dim3(4096 / 64, BT_DIM / 128), 256, GEMM_SMEM>>>(
        xh, WinTh, WinTl, xz, sz, nullptr, BT_DIM, 4096, 1024);
    // 3) conv along e + silu (+ fp16 copy)
    conv_silu_kernel<<<BT_DIM, 256>>>(xz, W_conv, xc, xch);
    // 4) W_dt transpose (hi only)
    tsplit_kernel<<<dim3(2048 / 32, 2048 / 32), 256>>>(W_dt, WdtTh, nullptr, 2048, 2048);
    // 5) dt projection (single-term) + softplus + clip   <-- ncu capture target
    gemm_mma<2, false><<<dim3(E_DIM / 64, BT_DIM / 128), 256, GEMM_SMEM>>>(
        xch, WdtTh, nullptr, dtb, nullptr, b_dt, BT_DIM, E_DIM, E_DIM);
    // 6-7) W_B / W_C splits
    tsplit_kernel<<<dim3(64 / 32, 2048 / 32), 256>>>(W_B, WbcH,             WbcL,             2048, 64);
    tsplit_kernel<<<dim3(64 / 32, 2048 / 32), 256>>>(W_C, WbcH + 64 * 2048, WbcL + 64 * 2048, 2048, 64);
    // 8) B/C projections (split, cheap)
    gemm_mma<3, true><<<dim3(2, BT_DIM / 128), 256, GEMM_SMEM>>>(
        xch, WbcH, WbcL, Bpp, Cpp, nullptr, BT_DIM, 128, 2048);
    // 9) W_out split
    tsplit_kernel<<<dim3(1024 / 32, 2048 / 32), 256>>>(W_out, WoutTh, WoutTl, 2048, 1024);
    // 10) selective scan (fuses y * silu(z), emits fp16)
    scan_kernel<<<B_DIM * (E_DIM / 16), 512>>>(xc, dtb, Bpp, Cpp, sz, A_log, ywh);
    // 11) out projection (split) -> d_out
    gemm_mma<0, true><<<dim3(D_DIM / 64, BT_DIM / 128), 256, GEMM_SMEM>>>(
        ywh, WoutTh, WoutTl, out, nullptr, nullptr, BT_DIM, D_DIM, E_DIM);
}